// round 3
// baseline (speedup 1.0000x reference)
#include <cuda_runtime.h>
#include <math.h>

// ---------------------------------------------------------------------------
// ParallelGatedScan  (B=8, T=2048, D=512, SD=256, OD=64, CHUNK=32)
// Plan:
//   pack:  W_all[512,704] = [gate_W | in_W | vW | kW | qW]
//   G1:    lin = x @ W_all + b_all                  (one pass over x)
//   scan1/2/3: gated chunked scan (sigmoid + (1-g)* applied inline)
//   G2:    scan_out = states @ out_W + out_b
//   bind:  sequential outer-product scan on v/k/q slices of lin
//   G3:    y = bind @ opout_W + opout_b + x + scan_out
//   LN:    out = layernorm(y) * ln_g + ln_b
// ---------------------------------------------------------------------------

#define Bm 8
#define Tm 2048
#define Dm 512
#define SDm 256
#define ODm 64
#define NW 704                 // fused width: 256 gate | 256 in | 64 v | 64 k | 64 q
#define COL_IN 256
#define COL_V 512
#define COL_K 576
#define COL_Q 640
#define CH 32
#define NCH (Tm / CH)          // 64
#define Mrows (Bm * Tm)        // 16384

// ------------------------- scratch (device globals) ------------------------
__device__ float g_lin[Mrows * NW];          // fused linear outputs (46 MB)
__device__ float g_states[Mrows * SDm];
__device__ float g_scanout[Mrows * Dm];
__device__ float g_bind[Mrows * ODm];
__device__ float g_y[Mrows * Dm];
__device__ float g_ca[Bm * NCH * SDm];
__device__ float g_wb[Bm * NCH * SDm];
__device__ float g_hprev[Bm * NCH * SDm];
__device__ float g_Wall[Dm * NW];
__device__ float g_ball[NW];

// --------------------------- weight packing ---------------------------------
__global__ void pack_kernel(
    const float* __restrict__ gW, const float* __restrict__ gb,
    const float* __restrict__ iW, const float* __restrict__ ib,
    const float* __restrict__ vW, const float* __restrict__ vb,
    const float* __restrict__ kW, const float* __restrict__ kb,
    const float* __restrict__ qW, const float* __restrict__ qb)
{
    int t = blockIdx.x * blockDim.x + threadIdx.x;     // Dm*NW = 360448
    if (t >= Dm * NW) return;
    int d = t / NW;
    int c = t % NW;
    float w, bv;
    if (c < COL_IN)      { w = gW[d * SDm + c];              bv = gb[c]; }
    else if (c < COL_V)  { w = iW[d * SDm + (c - COL_IN)];   bv = ib[c - COL_IN]; }
    else if (c < COL_K)  { w = vW[d * ODm + (c - COL_V)];    bv = vb[c - COL_V]; }
    else if (c < COL_Q)  { w = kW[d * ODm + (c - COL_K)];    bv = kb[c - COL_K]; }
    else                 { w = qW[d * ODm + (c - COL_Q)];    bv = qb[c - COL_Q]; }
    g_Wall[t] = w;
    if (d == 0) g_ball[c] = bv;
}

// ------------------------------- GEMM ---------------------------------------
// C[M,N] = A[M,K] @ B[K,N], tile 128x64x16, 256 threads, 8x4 microtile.
// ep: 0 = +bias ; 3 = +bias + aux1 + aux2 (residual add)
#define BMt 128
#define BNt 64
#define BKt 16

__global__ __launch_bounds__(256) void gemm_ep(
    const float* __restrict__ A, const float* __restrict__ B,
    const float* __restrict__ bias, float* __restrict__ C,
    int M, int N, int K, int ep,
    const float* __restrict__ aux1, const float* __restrict__ aux2)
{
    __shared__ float As[BKt][BMt + 4];
    __shared__ float Bs[BKt][BNt];

    const int bm = blockIdx.y * BMt;
    const int bn = blockIdx.x * BNt;
    const int tid = threadIdx.x;

    const int a_row = tid >> 1;          // 0..127
    const int a_k0  = (tid & 1) * 8;     // 0 or 8
    const int b_k   = tid >> 4;          // 0..15
    const int b_n0  = (tid & 15) * 4;

    const int tr = (tid >> 4) * 8;       // row base within tile
    const int tc = (tid & 15) * 4;       // col base within tile

    float acc[8][4];
    #pragma unroll
    for (int i = 0; i < 8; i++)
        #pragma unroll
        for (int j = 0; j < 4; j++) acc[i][j] = 0.f;

    for (int k0 = 0; k0 < K; k0 += BKt) {
        const float* Ap = A + (size_t)(bm + a_row) * K + k0 + a_k0;
        float4 a0 = *(const float4*)(Ap);
        float4 a1 = *(const float4*)(Ap + 4);
        As[a_k0 + 0][a_row] = a0.x;  As[a_k0 + 1][a_row] = a0.y;
        As[a_k0 + 2][a_row] = a0.z;  As[a_k0 + 3][a_row] = a0.w;
        As[a_k0 + 4][a_row] = a1.x;  As[a_k0 + 5][a_row] = a1.y;
        As[a_k0 + 6][a_row] = a1.z;  As[a_k0 + 7][a_row] = a1.w;
        const float* Bp = B + (size_t)(k0 + b_k) * N + bn + b_n0;
        *(float4*)&Bs[b_k][b_n0] = *(const float4*)Bp;
        __syncthreads();

        #pragma unroll
        for (int kk = 0; kk < BKt; kk++) {
            float4 b4  = *(const float4*)&Bs[kk][tc];
            float4 a4a = *(const float4*)&As[kk][tr];
            float4 a4b = *(const float4*)&As[kk][tr + 4];
            float av[8] = {a4a.x, a4a.y, a4a.z, a4a.w, a4b.x, a4b.y, a4b.z, a4b.w};
            float bv[4] = {b4.x, b4.y, b4.z, b4.w};
            #pragma unroll
            for (int i = 0; i < 8; i++)
                #pragma unroll
                for (int j = 0; j < 4; j++)
                    acc[i][j] = fmaf(av[i], bv[j], acc[i][j]);
        }
        __syncthreads();
    }

    float bv[4];
    #pragma unroll
    for (int j = 0; j < 4; j++) bv[j] = bias[bn + tc + j];

    #pragma unroll
    for (int i = 0; i < 8; i++) {
        const int row = bm + tr + i;
        const size_t off = (size_t)row * N + bn + tc;
        float r[4];
        #pragma unroll
        for (int j = 0; j < 4; j++) r[j] = acc[i][j] + bv[j];
        if (ep == 3) {
            #pragma unroll
            for (int j = 0; j < 4; j++) r[j] = r[j] + aux1[off + j] + aux2[off + j];
        }
        float4 o = {r[0], r[1], r[2], r[3]};
        *(float4*)&C[off] = o;
    }
}

// ----------------------------- gated scan -----------------------------------
// sigmoid + (1-g)*il applied inline; exact reference clamps.
__device__ __forceinline__ float sigmoidf_(float z) { return 1.f / (1.f + expf(-z)); }

// scan1: per-chunk summary (cum_a last, cum_wb last)
__global__ void scan1_kernel()
{
    int tid = blockIdx.x * blockDim.x + threadIdx.x;   // B*NCH*SD = 131072
    int sd = tid & (SDm - 1);
    int c  = (tid >> 8) & (NCH - 1);
    int b  = tid >> 14;
    size_t base = ((size_t)(b * Tm + c * CH)) * NW;
    float p = 1.f, wb = 0.f;
    #pragma unroll 4
    for (int k = 0; k < CH; k++) {
        size_t ro = base + (size_t)k * NW;
        float g = sigmoidf_(g_lin[ro + sd]);
        float d = (1.f - g) * g_lin[ro + COL_IN + sd];
        p *= fmaxf(g, 1e-6f);
        wb += d / fmaxf(p, 1e-8f);
    }
    int cidx = (b * NCH + c) * SDm + sd;
    g_ca[cidx] = p;
    g_wb[cidx] = wb;
}

// scan2: sequential carry over 64 chunks per (b, sd) lane
__global__ void scan2_kernel()
{
    int tid = blockIdx.x * blockDim.x + threadIdx.x;   // 2048
    int sd = tid & (SDm - 1);
    int b  = tid >> 8;
    float h = 0.f;
    for (int c = 0; c < NCH; c++) {
        int idx = (b * NCH + c) * SDm + sd;
        g_hprev[idx] = h;
        h = g_ca[idx] * (h + g_wb[idx]);
    }
}

// scan3: emit states per chunk using carried h
__global__ void scan3_kernel()
{
    int tid = blockIdx.x * blockDim.x + threadIdx.x;
    int sd = tid & (SDm - 1);
    int c  = (tid >> 8) & (NCH - 1);
    int b  = tid >> 14;
    size_t base  = ((size_t)(b * Tm + c * CH)) * NW;
    size_t sbase = ((size_t)(b * Tm + c * CH)) * SDm + sd;
    int cidx = (b * NCH + c) * SDm + sd;
    float h = g_hprev[cidx];
    float p = 1.f, wb = 0.f;
    #pragma unroll 4
    for (int k = 0; k < CH; k++) {
        size_t ro = base + (size_t)k * NW;
        float g = sigmoidf_(g_lin[ro + sd]);
        float d = (1.f - g) * g_lin[ro + COL_IN + sd];
        p *= fmaxf(g, 1e-6f);
        wb += d / fmaxf(p, 1e-8f);
        g_states[sbase + (size_t)k * SDm] = p * (h + wb);
    }
}

// ---------------------------- binding scan ----------------------------------
// S_t[i,j] = dec_i * S_{t-1}[i,j] + v_t[i] k_t[j];  o_t[i] = sum_j S_t[i,j] q_t[j]
// Rows i independent -> 16 rows x 16 col-groups per block, 4 blocks x 8 batches.
// Software-pipelined: prefetch t+1's v/k/q while computing step t.
__global__ __launch_bounds__(256) void bind_scan_kernel(const float* __restrict__ op_decay)
{
    const int b = blockIdx.y;
    const int i = blockIdx.x * 16 + (threadIdx.x >> 4);
    const int g = threadIdx.x & 15;
    const float dec = 1.f / (1.f + expf(-op_decay[i]));

    float4 S = {0.f, 0.f, 0.f, 0.f};
    const size_t base  = (size_t)b * Tm * NW;
    const size_t obase = (size_t)b * Tm * ODm;

    // prologue: load t=0
    float  vi = g_lin[base + COL_V + i];
    float4 kk = *(const float4*)&g_lin[base + COL_K + g * 4];
    float4 qq = *(const float4*)&g_lin[base + COL_Q + g * 4];

    for (int t = 0; t < Tm; t++) {
        float  vi_n = 0.f;
        float4 kk_n = {0, 0, 0, 0}, qq_n = {0, 0, 0, 0};
        if (t + 1 < Tm) {
            const size_t on = base + (size_t)(t + 1) * NW;
            vi_n = g_lin[on + COL_V + i];
            kk_n = *(const float4*)&g_lin[on + COL_K + g * 4];
            qq_n = *(const float4*)&g_lin[on + COL_Q + g * 4];
        }
        S.x = fmaf(vi, kk.x, dec * S.x);
        S.y = fmaf(vi, kk.y, dec * S.y);
        S.z = fmaf(vi, kk.z, dec * S.z);
        S.w = fmaf(vi, kk.w, dec * S.w);
        float part = fmaf(S.x, qq.x, fmaf(S.y, qq.y, fmaf(S.z, qq.z, S.w * qq.w)));
        part += __shfl_down_sync(0xffffffffu, part, 8);
        part += __shfl_down_sync(0xffffffffu, part, 4);
        part += __shfl_down_sync(0xffffffffu, part, 2);
        part += __shfl_down_sync(0xffffffffu, part, 1);
        if (g == 0) g_bind[obase + (size_t)t * ODm + i] = part;
        vi = vi_n; kk = kk_n; qq = qq_n;
    }
}

// ------------------------------- layernorm -----------------------------------
__global__ __launch_bounds__(128) void ln_kernel(
    const float* __restrict__ ln_g, const float* __restrict__ ln_b,
    float* __restrict__ out)
{
    const int row = blockIdx.x;
    const int tid = threadIdx.x;
    const float4* yr = (const float4*)(g_y + (size_t)row * Dm);
    float4 v = yr[tid];
    float s  = v.x + v.y + v.z + v.w;
    float s2 = v.x * v.x + v.y * v.y + v.z * v.z + v.w * v.w;
    #pragma unroll
    for (int off = 16; off; off >>= 1) {
        s  += __shfl_xor_sync(0xffffffffu, s,  off);
        s2 += __shfl_xor_sync(0xffffffffu, s2, off);
    }
    __shared__ float ss[4], ss2[4];
    if ((tid & 31) == 0) { ss[tid >> 5] = s; ss2[tid >> 5] = s2; }
    __syncthreads();
    s  = ss[0]  + ss[1]  + ss[2]  + ss[3];
    s2 = ss2[0] + ss2[1] + ss2[2] + ss2[3];
    const float mu   = s  * (1.f / Dm);
    const float var  = s2 * (1.f / Dm) - mu * mu;
    const float rstd = rsqrtf(var + 1e-5f);
    float4 gg = ((const float4*)ln_g)[tid];
    float4 bb = ((const float4*)ln_b)[tid];
    float4 r;
    r.x = (v.x - mu) * rstd * gg.x + bb.x;
    r.y = (v.y - mu) * rstd * gg.y + bb.y;
    r.z = (v.z - mu) * rstd * gg.z + bb.z;
    r.w = (v.w - mu) * rstd * gg.w + bb.w;
    ((float4*)(out + (size_t)row * Dm))[tid] = r;
}

// --------------------------------- host --------------------------------------
extern "C" void kernel_launch(void* const* d_in, const int* in_sizes, int n_in,
                              void* d_out, int out_size)
{
    const float* x       = (const float*)d_in[0];
    const float* gate_W  = (const float*)d_in[1];
    const float* gate_b  = (const float*)d_in[2];
    const float* in_W    = (const float*)d_in[3];
    const float* in_b    = (const float*)d_in[4];
    const float* out_W   = (const float*)d_in[5];
    const float* out_b   = (const float*)d_in[6];
    const float* opv_W   = (const float*)d_in[7];
    const float* opv_b   = (const float*)d_in[8];
    const float* opk_W   = (const float*)d_in[9];
    const float* opk_b   = (const float*)d_in[10];
    const float* opq_W   = (const float*)d_in[11];
    const float* opq_b   = (const float*)d_in[12];
    const float* op_dec  = (const float*)d_in[13];
    const float* opout_W = (const float*)d_in[14];
    const float* opout_b = (const float*)d_in[15];
    const float* ln_g    = (const float*)d_in[16];
    const float* ln_b    = (const float*)d_in[17];
    float* out = (float*)d_out;

    float *p_lin, *p_states, *p_scanout, *p_bind, *p_y, *p_Wall, *p_ball;
    cudaGetSymbolAddress((void**)&p_lin,     g_lin);
    cudaGetSymbolAddress((void**)&p_states,  g_states);
    cudaGetSymbolAddress((void**)&p_scanout, g_scanout);
    cudaGetSymbolAddress((void**)&p_bind,    g_bind);
    cudaGetSymbolAddress((void**)&p_y,       g_y);
    cudaGetSymbolAddress((void**)&p_Wall,    g_Wall);
    cudaGetSymbolAddress((void**)&p_ball,    g_ball);

    const dim3 blk(256);

    // 0) pack fused weights
    pack_kernel<<<(Dm * NW + 255) / 256, blk>>>(
        gate_W, gate_b, in_W, in_b, opv_W, opv_b, opk_W, opk_b, opq_W, opq_b);
    // 1) lin = x @ W_all + b_all   (N=704 = 11 tiles of 64)
    gemm_ep<<<dim3(NW / BNt, Mrows / BMt), blk>>>(
        x, p_Wall, p_ball, p_lin, Mrows, NW, Dm, 0, nullptr, nullptr);
    // 2) gated chunked scan
    scan1_kernel<<<(Bm * NCH * SDm) / 256, blk>>>();
    scan2_kernel<<<(Bm * SDm) / 256, blk>>>();
    scan3_kernel<<<(Bm * NCH * SDm) / 256, blk>>>();
    // 3) scan_out = states @ out_W + out_b
    gemm_ep<<<dim3(Dm / BNt, Mrows / BMt), blk>>>(
        p_states, out_W, out_b, p_scanout, Mrows, Dm, SDm, 0, nullptr, nullptr);
    // 4) binding scan
    bind_scan_kernel<<<dim3(4, Bm), blk>>>(op_dec);
    // 5) y = bind @ opout_W + opout_b + x + scan_out
    gemm_ep<<<dim3(Dm / BNt, Mrows / BMt), blk>>>(
        p_bind, opout_W, opout_b, p_y, Mrows, Dm, ODm, 3, x, p_scanout);
    // 6) layernorm -> out
    ln_kernel<<<Mrows, 128>>>(ln_g, ln_b, out);
}

// round 8
// speedup vs baseline: 1.1490x; 1.1490x over previous
#include <cuda_runtime.h>
#include <math.h>
#include <stdint.h>

// ---------------------------------------------------------------------------
// ParallelGatedScan  (B=8, T=2048, D=512, SD=256, OD=64, CHUNK=32)
//   pack:  W_all[512,768] = [gate_W | in_W | vW | kW | qW | zero-pad]
//   G1:    lin = x @ W_all + b_all            (tf32 tensor-core GEMM)
//   scan1/2/3: gated chunked scan (sigmoid + (1-g)* inline, exact clamps)
//   G2:    scan_out = states @ out_W + out_b  (tf32 GEMM)
//   bind:  sequential outer-product scan on v/k/q slices of lin
//   G3:    y = bind @ opout_W + opout_b + x + scan_out  (tf32 GEMM, fused)
//   LN:    out = layernorm(y) * ln_g + ln_b
// ---------------------------------------------------------------------------

#define Bm 8
#define Tm 2048
#define Dm 512
#define SDm 256
#define ODm 64
#define NW 768                 // padded fused width (704 real)
#define NW_REAL 704
#define COL_IN 256
#define COL_V 512
#define COL_K 576
#define COL_Q 640
#define CH 32
#define NCH (Tm / CH)          // 64
#define Mrows (Bm * Tm)        // 16384

// ------------------------- scratch (device globals) ------------------------
__device__ float g_lin[Mrows * NW];          // 50 MB
__device__ float g_states[Mrows * SDm];
__device__ float g_scanout[Mrows * Dm];
__device__ float g_bind[Mrows * ODm];
__device__ float g_y[Mrows * Dm];
__device__ float g_ca[Bm * NCH * SDm];
__device__ float g_wb[Bm * NCH * SDm];
__device__ float g_hprev[Bm * NCH * SDm];
__device__ float g_Wall[Dm * NW];
__device__ float g_ball[NW];

// --------------------------- weight packing ---------------------------------
__global__ void pack_kernel(
    const float* __restrict__ gW, const float* __restrict__ gb,
    const float* __restrict__ iW, const float* __restrict__ ib,
    const float* __restrict__ vW, const float* __restrict__ vb,
    const float* __restrict__ kW, const float* __restrict__ kb,
    const float* __restrict__ qW, const float* __restrict__ qb)
{
    int t = blockIdx.x * blockDim.x + threadIdx.x;     // Dm*NW = 393216
    if (t >= Dm * NW) return;
    int d = t / NW;
    int c = t % NW;
    float w = 0.f, bv = 0.f;
    if (c < COL_IN)        { w = gW[d * SDm + c];              bv = gb[c]; }
    else if (c < COL_V)    { w = iW[d * SDm + (c - COL_IN)];   bv = ib[c - COL_IN]; }
    else if (c < COL_K)    { w = vW[d * ODm + (c - COL_V)];    bv = vb[c - COL_V]; }
    else if (c < COL_Q)    { w = kW[d * ODm + (c - COL_K)];    bv = kb[c - COL_K]; }
    else if (c < NW_REAL)  { w = qW[d * ODm + (c - COL_Q)];    bv = qb[c - COL_Q]; }
    g_Wall[t] = w;
    if (d == 0) g_ball[c] = bv;
}

// ------------------------- tf32 tensor-core GEMM -----------------------------
// C[M,N] = A[M,K] @ B[K,N]; block tile 128x128x32; 8 warps as 2x4; warp 64x32.
// mma.sync.aligned.m16n8k8 tf32, fp32 accumulate. RNA rounding at stage time.
// ep: 0 = +bias ; 3 = +bias + aux1 + aux2
#define TMt 128
#define TNt 128
#define TKt 32
#define AP  36      // As row pad  -> frag-load bank = (4g+tig)%32, conflict-free
#define BP  136     // Bs row pad  -> frag-load bank = (8tig+g)%32, conflict-free

__device__ __forceinline__ uint32_t f2tf(float f)
{
    uint32_t r;
    asm("cvt.rna.tf32.f32 %0, %1;" : "=r"(r) : "f"(f));
    return r;
}

__global__ __launch_bounds__(256) void gemm_tc(
    const float* __restrict__ A, const float* __restrict__ B,
    const float* __restrict__ bias, float* __restrict__ C,
    int M, int N, int K, int ep,
    const float* __restrict__ aux1, const float* __restrict__ aux2)
{
    __shared__ float As[TMt * AP];
    __shared__ float Bs[TKt * BP];

    const int tid  = threadIdx.x;
    const int bm   = blockIdx.y * TMt;
    const int bn   = blockIdx.x * TNt;
    const int lane = tid & 31;
    const int w    = tid >> 5;
    const int g    = lane >> 2;        // groupID
    const int tig  = lane & 3;         // thread-in-group
    const int wm   = (w >> 2) * 64;    // warp m offset (0 or 64)
    const int wn   = (w & 3) * 32;     // warp n offset (0..96)

    float c[4][4][4];
    #pragma unroll
    for (int im = 0; im < 4; im++)
        #pragma unroll
        for (int in_ = 0; in_ < 4; in_++)
            #pragma unroll
            for (int r = 0; r < 4; r++) c[im][in_][r] = 0.f;

    for (int k0 = 0; k0 < K; k0 += TKt) {
        // stage global -> registers
        float4 av[4], bv4[4];
        #pragma unroll
        for (int j = 0; j < 4; j++) {
            int idx = j * 256 + tid;
            av[j]  = *(const float4*)&A[(size_t)(bm + (idx >> 3)) * K + k0 + ((idx & 7) << 2)];
            bv4[j] = *(const float4*)&B[(size_t)(k0 + (idx >> 5)) * N + bn + ((idx & 31) << 2)];
        }
        __syncthreads();   // previous-iteration consumers done before overwrite
        #pragma unroll
        for (int j = 0; j < 4; j++) {
            int idx = j * 256 + tid;
            uint4 ua = { f2tf(av[j].x),  f2tf(av[j].y),  f2tf(av[j].z),  f2tf(av[j].w) };
            uint4 ub = { f2tf(bv4[j].x), f2tf(bv4[j].y), f2tf(bv4[j].z), f2tf(bv4[j].w) };
            *(uint4*)&As[(idx >> 3) * AP + ((idx & 7) << 2)]  = ua;
            *(uint4*)&Bs[(idx >> 5) * BP + ((idx & 31) << 2)] = ub;
        }
        __syncthreads();

        #pragma unroll
        for (int ks = 0; ks < 4; ks++) {
            const int kb = ks * 8;
            uint32_t af[4][4], bf[4][2];
            #pragma unroll
            for (int im = 0; im < 4; im++) {
                const int mb = wm + im * 16;
                af[im][0] = __float_as_uint(As[(mb + g)     * AP + kb + tig]);
                af[im][1] = __float_as_uint(As[(mb + g + 8) * AP + kb + tig]);
                af[im][2] = __float_as_uint(As[(mb + g)     * AP + kb + tig + 4]);
                af[im][3] = __float_as_uint(As[(mb + g + 8) * AP + kb + tig + 4]);
            }
            #pragma unroll
            for (int in_ = 0; in_ < 4; in_++) {
                const int nb = wn + in_ * 8;
                bf[in_][0] = __float_as_uint(Bs[(kb + tig)     * BP + nb + g]);
                bf[in_][1] = __float_as_uint(Bs[(kb + tig + 4) * BP + nb + g]);
            }
            #pragma unroll
            for (int im = 0; im < 4; im++)
                #pragma unroll
                for (int in_ = 0; in_ < 4; in_++)
                    asm volatile(
                        "mma.sync.aligned.m16n8k8.row.col.f32.tf32.tf32.f32 "
                        "{%0,%1,%2,%3},{%4,%5,%6,%7},{%8,%9},{%0,%1,%2,%3};"
                        : "+f"(c[im][in_][0]), "+f"(c[im][in_][1]),
                          "+f"(c[im][in_][2]), "+f"(c[im][in_][3])
                        : "r"(af[im][0]), "r"(af[im][1]), "r"(af[im][2]), "r"(af[im][3]),
                          "r"(bf[in_][0]), "r"(bf[in_][1]));
        }
    }

    // epilogue
    #pragma unroll
    for (int im = 0; im < 4; im++) {
        const int r0 = bm + wm + im * 16 + g;
        #pragma unroll
        for (int in_ = 0; in_ < 4; in_++) {
            const int col = bn + wn + in_ * 8 + 2 * tig;
            const float b0 = bias[col], b1 = bias[col + 1];
            const size_t o0 = (size_t)r0 * N + col;
            const size_t o1 = (size_t)(r0 + 8) * N + col;
            float v0 = c[im][in_][0] + b0;
            float v1 = c[im][in_][1] + b1;
            float v2 = c[im][in_][2] + b0;
            float v3 = c[im][in_][3] + b1;
            if (ep == 3) {
                v0 += aux1[o0]     + aux2[o0];
                v1 += aux1[o0 + 1] + aux2[o0 + 1];
                v2 += aux1[o1]     + aux2[o1];
                v3 += aux1[o1 + 1] + aux2[o1 + 1];
            }
            float2 w0 = {v0, v1}, w1 = {v2, v3};
            *(float2*)&C[o0] = w0;
            *(float2*)&C[o1] = w1;
        }
    }
}

// ----------------------------- gated scan -----------------------------------
__device__ __forceinline__ float sigmoidf_(float z) { return 1.f / (1.f + expf(-z)); }

// scan1: per-chunk summary (cum_a last, cum_wb last), exact reference clamps
__global__ void scan1_kernel()
{
    int tid = blockIdx.x * blockDim.x + threadIdx.x;   // B*NCH*SD = 131072
    int sd = tid & (SDm - 1);
    int c  = (tid >> 8) & (NCH - 1);
    int b  = tid >> 14;
    size_t base = ((size_t)(b * Tm + c * CH)) * NW;
    float p = 1.f, wb = 0.f;
    for (int k = 0; k < CH; k++) {
        size_t ro = base + (size_t)k * NW;
        float g = sigmoidf_(g_lin[ro + sd]);
        float d = (1.f - g) * g_lin[ro + COL_IN + sd];
        p *= fmaxf(g, 1e-6f);
        wb += d / fmaxf(p, 1e-8f);
    }
    int cidx = (b * NCH + c) * SDm + sd;
    g_ca[cidx] = p;
    g_wb[cidx] = wb;
}

// scan2: sequential carry over 64 chunks, software-pipelined loads
__global__ void scan2_kernel()
{
    int t  = blockIdx.x * blockDim.x + threadIdx.x;    // 2048 lanes
    int sd = t & (SDm - 1);
    int b  = t >> 8;
    const int base = b * NCH * SDm + sd;
    float h  = 0.f;
    float ca = g_ca[base], wb = g_wb[base];
    #pragma unroll 8
    for (int c = 0; c < NCH; c++) {
        float ca_n = 0.f, wb_n = 0.f;
        if (c + 1 < NCH) {
            ca_n = g_ca[base + (c + 1) * SDm];
            wb_n = g_wb[base + (c + 1) * SDm];
        }
        g_hprev[base + c * SDm] = h;
        h = ca * (h + wb);
        ca = ca_n; wb = wb_n;
    }
}

// scan3: emit states per chunk using carried h
__global__ void scan3_kernel()
{
    int tid = blockIdx.x * blockDim.x + threadIdx.x;
    int sd = tid & (SDm - 1);
    int c  = (tid >> 8) & (NCH - 1);
    int b  = tid >> 14;
    size_t base  = ((size_t)(b * Tm + c * CH)) * NW;
    size_t sbase = ((size_t)(b * Tm + c * CH)) * SDm + sd;
    int cidx = (b * NCH + c) * SDm + sd;
    float h = g_hprev[cidx];
    float p = 1.f, wb = 0.f;
    for (int k = 0; k < CH; k++) {
        size_t ro = base + (size_t)k * NW;
        float g = sigmoidf_(g_lin[ro + sd]);
        float d = (1.f - g) * g_lin[ro + COL_IN + sd];
        p *= fmaxf(g, 1e-6f);
        wb += d / fmaxf(p, 1e-8f);
        g_states[sbase + (size_t)k * SDm] = p * (h + wb);
    }
}

// ---------------------------- binding scan ----------------------------------
// S_t[i,j] = dec_i * S_{t-1}[i,j] + v_t[i] k_t[j];  o_t[i] = sum_j S_t[i,j] q_t[j]
__global__ __launch_bounds__(256) void bind_scan_kernel(const float* __restrict__ op_decay)
{
    const int b = blockIdx.y;
    const int i = blockIdx.x * 16 + (threadIdx.x >> 4);
    const int g = threadIdx.x & 15;
    const float dec = 1.f / (1.f + expf(-op_decay[i]));

    float4 S = {0.f, 0.f, 0.f, 0.f};
    const size_t base  = (size_t)b * Tm * NW;
    const size_t obase = (size_t)b * Tm * ODm;

    float  vi = g_lin[base + COL_V + i];
    float4 kk = *(const float4*)&g_lin[base + COL_K + g * 4];
    float4 qq = *(const float4*)&g_lin[base + COL_Q + g * 4];

    for (int t = 0; t < Tm; t++) {
        float  vi_n = 0.f;
        float4 kk_n = {0, 0, 0, 0}, qq_n = {0, 0, 0, 0};
        if (t + 1 < Tm) {
            const size_t on = base + (size_t)(t + 1) * NW;
            vi_n = g_lin[on + COL_V + i];
            kk_n = *(const float4*)&g_lin[on + COL_K + g * 4];
            qq_n = *(const float4*)&g_lin[on + COL_Q + g * 4];
        }
        S.x = fmaf(vi, kk.x, dec * S.x);
        S.y = fmaf(vi, kk.y, dec * S.y);
        S.z = fmaf(vi, kk.z, dec * S.z);
        S.w = fmaf(vi, kk.w, dec * S.w);
        float part = fmaf(S.x, qq.x, fmaf(S.y, qq.y, fmaf(S.z, qq.z, S.w * qq.w)));
        part += __shfl_down_sync(0xffffffffu, part, 8);
        part += __shfl_down_sync(0xffffffffu, part, 4);
        part += __shfl_down_sync(0xffffffffu, part, 2);
        part += __shfl_down_sync(0xffffffffu, part, 1);
        if (g == 0) g_bind[obase + (size_t)t * ODm + i] = part;
        vi = vi_n; kk = kk_n; qq = qq_n;
    }
}

// ------------------------------- layernorm -----------------------------------
__global__ __launch_bounds__(128) void ln_kernel(
    const float* __restrict__ ln_g, const float* __restrict__ ln_b,
    float* __restrict__ out)
{
    const int row = blockIdx.x;
    const int tid = threadIdx.x;
    const float4* yr = (const float4*)(g_y + (size_t)row * Dm);
    float4 v = yr[tid];
    float s  = v.x + v.y + v.z + v.w;
    float s2 = v.x * v.x + v.y * v.y + v.z * v.z + v.w * v.w;
    #pragma unroll
    for (int off = 16; off; off >>= 1) {
        s  += __shfl_xor_sync(0xffffffffu, s,  off);
        s2 += __shfl_xor_sync(0xffffffffu, s2, off);
    }
    __shared__ float ss[4], ss2[4];
    if ((tid & 31) == 0) { ss[tid >> 5] = s; ss2[tid >> 5] = s2; }
    __syncthreads();
    s  = ss[0]  + ss[1]  + ss[2]  + ss[3];
    s2 = ss2[0] + ss2[1] + ss2[2] + ss2[3];
    const float mu   = s  * (1.f / Dm);
    const float var  = s2 * (1.f / Dm) - mu * mu;
    const float rstd = rsqrtf(var + 1e-5f);
    float4 gg = ((const float4*)ln_g)[tid];
    float4 bb = ((const float4*)ln_b)[tid];
    float4 r;
    r.x = (v.x - mu) * rstd * gg.x + bb.x;
    r.y = (v.y - mu) * rstd * gg.y + bb.y;
    r.z = (v.z - mu) * rstd * gg.z + bb.z;
    r.w = (v.w - mu) * rstd * gg.w + bb.w;
    ((float4*)(out + (size_t)row * Dm))[tid] = r;
}

// --------------------------------- host --------------------------------------
extern "C" void kernel_launch(void* const* d_in, const int* in_sizes, int n_in,
                              void* d_out, int out_size)
{
    const float* x       = (const float*)d_in[0];
    const float* gate_W  = (const float*)d_in[1];
    const float* gate_b  = (const float*)d_in[2];
    const float* in_W    = (const float*)d_in[3];
    const float* in_b    = (const float*)d_in[4];
    const float* out_W   = (const float*)d_in[5];
    const float* out_b   = (const float*)d_in[6];
    const float* opv_W   = (const float*)d_in[7];
    const float* opv_b   = (const float*)d_in[8];
    const float* opk_W   = (const float*)d_in[9];
    const float* opk_b   = (const float*)d_in[10];
    const float* opq_W   = (const float*)d_in[11];
    const float* opq_b   = (const float*)d_in[12];
    const float* op_dec  = (const float*)d_in[13];
    const float* opout_W = (const float*)d_in[14];
    const float* opout_b = (const float*)d_in[15];
    const float* ln_g    = (const float*)d_in[16];
    const float* ln_b    = (const float*)d_in[17];
    float* out = (float*)d_out;

    float *p_lin, *p_states, *p_scanout, *p_bind, *p_y, *p_Wall, *p_ball;
    cudaGetSymbolAddress((void**)&p_lin,     g_lin);
    cudaGetSymbolAddress((void**)&p_states,  g_states);
    cudaGetSymbolAddress((void**)&p_scanout, g_scanout);
    cudaGetSymbolAddress((void**)&p_bind,    g_bind);
    cudaGetSymbolAddress((void**)&p_y,       g_y);
    cudaGetSymbolAddress((void**)&p_Wall,    g_Wall);
    cudaGetSymbolAddress((void**)&p_ball,    g_ball);

    const dim3 blk(256);

    // 0) pack fused weights (zero-padded to 768 cols)
    pack_kernel<<<(Dm * NW + 255) / 256, blk>>>(
        gate_W, gate_b, in_W, in_b, opv_W, opv_b, opk_W, opk_b, opq_W, opq_b);
    // 1) lin = x @ W_all + b_all   [16384 x 768] = [16384 x 512] @ [512 x 768]
    gemm_tc<<<dim3(NW / TNt, Mrows / TMt), blk>>>(
        x, p_Wall, p_ball, p_lin, Mrows, NW, Dm, 0, nullptr, nullptr);
    // 2) gated chunked scan
    scan1_kernel<<<(Bm * NCH * SDm) / 256, blk>>>();
    scan2_kernel<<<(Bm * SDm) / 64, 64>>>();
    scan3_kernel<<<(Bm * NCH * SDm) / 256, blk>>>();
    // 3) scan_out = states @ out_W + out_b
    gemm_tc<<<dim3(Dm / TNt, Mrows / TMt), blk>>>(
        p_states, out_W, out_b, p_scanout, Mrows, Dm, SDm, 0, nullptr, nullptr);
    // 4) binding scan
    bind_scan_kernel<<<dim3(4, Bm), blk>>>(op_dec);
    // 5) y = bind @ opout_W + opout_b + x + scan_out
    gemm_tc<<<dim3(Dm / TNt, Mrows / TMt), blk>>>(
        p_bind, opout_W, opout_b, p_y, Mrows, Dm, ODm, 3, x, p_scanout);
    // 6) layernorm -> out
    ln_kernel<<<Mrows, 128>>>(ln_g, ln_b, out);
}

// round 12
// speedup vs baseline: 3.9922x; 3.4744x over previous
#include <cuda_runtime.h>
#include <math.h>
#include <stdint.h>

// ---------------------------------------------------------------------------
// ParallelGatedScan  (B=8, T=2048, D=512, SD=256, OD=64, CHUNK=32)
//   pack:  W_all[512,768] = [gate_W | in_W | vW | kW | qW | zero-pad]
//   G1:    lin = x @ W_all + b_all            (tf32 tensor-core GEMM)
//   scan1/2/3: gated chunked scan
//   bind1/2/3: CHUNKED binding scan (parallel, replaces 2048-step serial loop)
//   G2:    scan_out = states @ out_W + out_b  (tf32 GEMM)
//   G3:    y = bind @ opout_W + opout_b + x + scan_out  (tf32 GEMM, fused)
//   LN:    out = layernorm(y) * ln_g + ln_b
// ---------------------------------------------------------------------------

#define Bm 8
#define Tm 2048
#define Dm 512
#define SDm 256
#define ODm 64
#define NW 768                 // padded fused width (704 real)
#define NW_REAL 704
#define COL_IN 256
#define COL_V 512
#define COL_K 576
#define COL_Q 640
#define CH 32
#define NCH (Tm / CH)          // 64
#define Mrows (Bm * Tm)        // 16384

// ------------------------- scratch (device globals) ------------------------
__device__ float g_lin[Mrows * NW];          // 50 MB
__device__ float g_states[Mrows * SDm];
__device__ float g_scanout[Mrows * Dm];
__device__ float g_bind[Mrows * ODm];
__device__ float g_y[Mrows * Dm];
__device__ float g_ca[Bm * NCH * SDm];
__device__ float g_wb[Bm * NCH * SDm];
__device__ float g_hprev[Bm * NCH * SDm];
__device__ float g_Wall[Dm * NW];
__device__ float g_ball[NW];
__device__ float g_Sloc[Bm * NCH * ODm * ODm];   // 8.4 MB chunk summaries
__device__ float g_Sprev[Bm * NCH * ODm * ODm];  // 8.4 MB carried states

// --------------------------- weight packing ---------------------------------
__global__ void pack_kernel(
    const float* __restrict__ gW, const float* __restrict__ gb,
    const float* __restrict__ iW, const float* __restrict__ ib,
    const float* __restrict__ vW, const float* __restrict__ vb,
    const float* __restrict__ kW, const float* __restrict__ kb,
    const float* __restrict__ qW, const float* __restrict__ qb)
{
    int t = blockIdx.x * blockDim.x + threadIdx.x;
    if (t >= Dm * NW) return;
    int d = t / NW;
    int c = t % NW;
    float w = 0.f, bv = 0.f;
    if (c < COL_IN)        { w = gW[d * SDm + c];              bv = gb[c]; }
    else if (c < COL_V)    { w = iW[d * SDm + (c - COL_IN)];   bv = ib[c - COL_IN]; }
    else if (c < COL_K)    { w = vW[d * ODm + (c - COL_V)];    bv = vb[c - COL_V]; }
    else if (c < COL_Q)    { w = kW[d * ODm + (c - COL_K)];    bv = kb[c - COL_K]; }
    else if (c < NW_REAL)  { w = qW[d * ODm + (c - COL_Q)];    bv = qb[c - COL_Q]; }
    g_Wall[t] = w;
    if (d == 0) g_ball[c] = bv;
}

// ------------------------- tf32 tensor-core GEMM -----------------------------
#define TMt 128
#define TNt 128
#define TKt 32
#define AP  36
#define BP  136

__device__ __forceinline__ uint32_t f2tf(float f)
{
    uint32_t r;
    asm("cvt.rna.tf32.f32 %0, %1;" : "=r"(r) : "f"(f));
    return r;
}

__global__ __launch_bounds__(256) void gemm_tc(
    const float* __restrict__ A, const float* __restrict__ B,
    const float* __restrict__ bias, float* __restrict__ C,
    int M, int N, int K, int ep,
    const float* __restrict__ aux1, const float* __restrict__ aux2)
{
    __shared__ float As[TMt * AP];
    __shared__ float Bs[TKt * BP];

    const int tid  = threadIdx.x;
    const int bm   = blockIdx.y * TMt;
    const int bn   = blockIdx.x * TNt;
    const int lane = tid & 31;
    const int w    = tid >> 5;
    const int g    = lane >> 2;
    const int tig  = lane & 3;
    const int wm   = (w >> 2) * 64;
    const int wn   = (w & 3) * 32;

    float c[4][4][4];
    #pragma unroll
    for (int im = 0; im < 4; im++)
        #pragma unroll
        for (int in_ = 0; in_ < 4; in_++)
            #pragma unroll
            for (int r = 0; r < 4; r++) c[im][in_][r] = 0.f;

    for (int k0 = 0; k0 < K; k0 += TKt) {
        float4 av[4], bv4[4];
        #pragma unroll
        for (int j = 0; j < 4; j++) {
            int idx = j * 256 + tid;
            av[j]  = *(const float4*)&A[(size_t)(bm + (idx >> 3)) * K + k0 + ((idx & 7) << 2)];
            bv4[j] = *(const float4*)&B[(size_t)(k0 + (idx >> 5)) * N + bn + ((idx & 31) << 2)];
        }
        __syncthreads();
        #pragma unroll
        for (int j = 0; j < 4; j++) {
            int idx = j * 256 + tid;
            uint4 ua = { f2tf(av[j].x),  f2tf(av[j].y),  f2tf(av[j].z),  f2tf(av[j].w) };
            uint4 ub = { f2tf(bv4[j].x), f2tf(bv4[j].y), f2tf(bv4[j].z), f2tf(bv4[j].w) };
            *(uint4*)&As[(idx >> 3) * AP + ((idx & 7) << 2)]  = ua;
            *(uint4*)&Bs[(idx >> 5) * BP + ((idx & 31) << 2)] = ub;
        }
        __syncthreads();

        #pragma unroll
        for (int ks = 0; ks < 4; ks++) {
            const int kb = ks * 8;
            uint32_t af[4][4], bf[4][2];
            #pragma unroll
            for (int im = 0; im < 4; im++) {
                const int mb = wm + im * 16;
                af[im][0] = __float_as_uint(As[(mb + g)     * AP + kb + tig]);
                af[im][1] = __float_as_uint(As[(mb + g + 8) * AP + kb + tig]);
                af[im][2] = __float_as_uint(As[(mb + g)     * AP + kb + tig + 4]);
                af[im][3] = __float_as_uint(As[(mb + g + 8) * AP + kb + tig + 4]);
            }
            #pragma unroll
            for (int in_ = 0; in_ < 4; in_++) {
                const int nb = wn + in_ * 8;
                bf[in_][0] = __float_as_uint(Bs[(kb + tig)     * BP + nb + g]);
                bf[in_][1] = __float_as_uint(Bs[(kb + tig + 4) * BP + nb + g]);
            }
            #pragma unroll
            for (int im = 0; im < 4; im++)
                #pragma unroll
                for (int in_ = 0; in_ < 4; in_++)
                    asm volatile(
                        "mma.sync.aligned.m16n8k8.row.col.f32.tf32.tf32.f32 "
                        "{%0,%1,%2,%3},{%4,%5,%6,%7},{%8,%9},{%0,%1,%2,%3};"
                        : "+f"(c[im][in_][0]), "+f"(c[im][in_][1]),
                          "+f"(c[im][in_][2]), "+f"(c[im][in_][3])
                        : "r"(af[im][0]), "r"(af[im][1]), "r"(af[im][2]), "r"(af[im][3]),
                          "r"(bf[in_][0]), "r"(bf[in_][1]));
        }
    }

    #pragma unroll
    for (int im = 0; im < 4; im++) {
        const int r0 = bm + wm + im * 16 + g;
        #pragma unroll
        for (int in_ = 0; in_ < 4; in_++) {
            const int col = bn + wn + in_ * 8 + 2 * tig;
            const float b0 = bias[col], b1 = bias[col + 1];
            const size_t o0 = (size_t)r0 * N + col;
            const size_t o1 = (size_t)(r0 + 8) * N + col;
            float v0 = c[im][in_][0] + b0;
            float v1 = c[im][in_][1] + b1;
            float v2 = c[im][in_][2] + b0;
            float v3 = c[im][in_][3] + b1;
            if (ep == 3) {
                v0 += aux1[o0]     + aux2[o0];
                v1 += aux1[o0 + 1] + aux2[o0 + 1];
                v2 += aux1[o1]     + aux2[o1];
                v3 += aux1[o1 + 1] + aux2[o1 + 1];
            }
            float2 w0 = {v0, v1}, w1 = {v2, v3};
            *(float2*)&C[o0] = w0;
            *(float2*)&C[o1] = w1;
        }
    }
}

// ----------------------------- gated scan -----------------------------------
__device__ __forceinline__ float sigmoidf_(float z) { return 1.f / (1.f + expf(-z)); }

__global__ void scan1_kernel()
{
    int tid = blockIdx.x * blockDim.x + threadIdx.x;
    int sd = tid & (SDm - 1);
    int c  = (tid >> 8) & (NCH - 1);
    int b  = tid >> 14;
    size_t base = ((size_t)(b * Tm + c * CH)) * NW;
    float p = 1.f, wb = 0.f;
    for (int k = 0; k < CH; k++) {
        size_t ro = base + (size_t)k * NW;
        float g = sigmoidf_(g_lin[ro + sd]);
        float d = (1.f - g) * g_lin[ro + COL_IN + sd];
        p *= fmaxf(g, 1e-6f);
        wb += d / fmaxf(p, 1e-8f);
    }
    int cidx = (b * NCH + c) * SDm + sd;
    g_ca[cidx] = p;
    g_wb[cidx] = wb;
}

__global__ void scan2_kernel()
{
    int t  = blockIdx.x * blockDim.x + threadIdx.x;
    int sd = t & (SDm - 1);
    int b  = t >> 8;
    const int base = b * NCH * SDm + sd;
    float h  = 0.f;
    float ca = g_ca[base], wb = g_wb[base];
    #pragma unroll 8
    for (int c = 0; c < NCH; c++) {
        float ca_n = 0.f, wb_n = 0.f;
        if (c + 1 < NCH) {
            ca_n = g_ca[base + (c + 1) * SDm];
            wb_n = g_wb[base + (c + 1) * SDm];
        }
        g_hprev[base + c * SDm] = h;
        h = ca * (h + wb);
        ca = ca_n; wb = wb_n;
    }
}

__global__ void scan3_kernel()
{
    int tid = blockIdx.x * blockDim.x + threadIdx.x;
    int sd = tid & (SDm - 1);
    int c  = (tid >> 8) & (NCH - 1);
    int b  = tid >> 14;
    size_t base  = ((size_t)(b * Tm + c * CH)) * NW;
    size_t sbase = ((size_t)(b * Tm + c * CH)) * SDm + sd;
    int cidx = (b * NCH + c) * SDm + sd;
    float h = g_hprev[cidx];
    float p = 1.f, wb = 0.f;
    for (int k = 0; k < CH; k++) {
        size_t ro = base + (size_t)k * NW;
        float g = sigmoidf_(g_lin[ro + sd]);
        float d = (1.f - g) * g_lin[ro + COL_IN + sd];
        p *= fmaxf(g, 1e-6f);
        wb += d / fmaxf(p, 1e-8f);
        g_states[sbase + (size_t)k * SDm] = p * (h + wb);
    }
}

// ------------------------ chunked binding scan -------------------------------
// S_t[i][j] = dec_i S_{t-1}[i][j] + v_t[i] k_t[j];  o_t[i] = sum_j S_t[i][j] q_t[j]
// bind1: per-chunk summary S_loc[i][j] = sum_s dec_i^{31-s} v_s[i] k_s[j]
__global__ __launch_bounds__(256) void bind1_kernel(const float* __restrict__ op_decay)
{
    const int c = blockIdx.x, b = blockIdx.y;
    const int tid = threadIdx.x;
    __shared__ float pw[CH + 1][ODm];     // dec_i^e, e = 0..32
    __shared__ float ksm[CH][ODm];
    __shared__ float wsm[CH][ODm];        // v_s[i] * dec_i^{31-s}

    if (tid < ODm) {
        float d = sigmoidf_(op_decay[tid]);
        float f = 1.f;
        for (int e = 0; e <= CH; e++) { pw[e][tid] = f; f *= d; }
    }
    __syncthreads();

    const size_t base = ((size_t)(b * Tm + c * CH)) * NW;
    for (int idx = tid; idx < CH * ODm; idx += 256) {
        int s = idx >> 6, i = idx & 63;
        ksm[s][i] = g_lin[base + (size_t)s * NW + COL_K + i];
        wsm[s][i] = g_lin[base + (size_t)s * NW + COL_V + i] * pw[31 - s][i];
    }
    __syncthreads();

    const int j  = tid & 63;
    const int ig = tid >> 6;              // 0..3, i range [ig*16, ig*16+16)
    float acc[16];
    #pragma unroll
    for (int r = 0; r < 16; r++) acc[r] = 0.f;
    for (int s = 0; s < CH; s++) {
        float kv = ksm[s][j];
        #pragma unroll
        for (int r = 0; r < 16; r++) acc[r] = fmaf(wsm[s][ig * 16 + r], kv, acc[r]);
    }
    float* dst = &g_Sloc[((size_t)(b * NCH + c)) * (ODm * ODm)];
    #pragma unroll
    for (int r = 0; r < 16; r++) dst[(ig * 16 + r) * ODm + j] = acc[r];
}

// bind2: carry S across chunks: S_prev[c] emitted, S = dec^32 (.) S + S_loc[c]
__global__ void bind2_kernel(const float* __restrict__ op_decay)
{
    int lane = blockIdx.x * blockDim.x + threadIdx.x;   // Bm*64*64 = 32768
    int b = lane >> 12;
    int i = (lane >> 6) & 63;
    float d = sigmoidf_(op_decay[i]);
    float d2 = d * d, d4 = d2 * d2, d8 = d4 * d4, d16 = d8 * d8, d32 = d16 * d16;
    const size_t base = (size_t)b * NCH * (ODm * ODm) + (lane & 4095);
    float h = 0.f;
    float sl = g_Sloc[base];
    #pragma unroll 8
    for (int c = 0; c < NCH; c++) {
        float sl_n = 0.f;
        if (c + 1 < NCH) sl_n = g_Sloc[base + (size_t)(c + 1) * (ODm * ODm)];
        g_Sprev[base + (size_t)c * (ODm * ODm)] = h;
        h = d32 * h + sl;
        sl = sl_n;
    }
}

// bind3: per chunk, o_t[i] = dec_i^{u+1} (S_prev q_t)[i] + sum_{s<=u} dec_i^{u-s} (k_s.q_t) v_s[i]
__global__ __launch_bounds__(256) void bind3_kernel(const float* __restrict__ op_decay)
{
    const int c = blockIdx.x, b = blockIdx.y;
    const int tid = threadIdx.x;
    __shared__ float ksm[CH][ODm];        // 8 KB
    __shared__ float qsmT[ODm][CH];       // transposed q: [j][u], 8 KB
    __shared__ float vsm[CH][ODm];        // 8 KB
    __shared__ float Ssm[ODm][ODm + 1];   // 16.25 KB
    __shared__ float Asm[CH][CH + 1];     // 4.1 KB

    const size_t base = ((size_t)(b * Tm + c * CH)) * NW;
    for (int idx = tid; idx < CH * ODm; idx += 256) {
        int s = idx >> 6, i = idx & 63;
        ksm[s][i]  = g_lin[base + (size_t)s * NW + COL_K + i];
        vsm[s][i]  = g_lin[base + (size_t)s * NW + COL_V + i];
        qsmT[i][s] = g_lin[base + (size_t)s * NW + COL_Q + i];
    }
    const float* Sp = &g_Sprev[((size_t)(b * NCH + c)) * (ODm * ODm)];
    for (int idx = tid; idx < ODm * ODm; idx += 256) {
        Ssm[idx >> 6][idx & 63] = Sp[idx];
    }
    __syncthreads();

    // scores: warp w computes A[all u][s in 4w..4w+3]
    {
        const int u  = tid & 31;
        const int s0 = (tid >> 5) * 4;
        float a0 = 0.f, a1 = 0.f, a2 = 0.f, a3 = 0.f;
        for (int j = 0; j < ODm; j++) {
            float qv = qsmT[j][u];
            a0 = fmaf(ksm[s0 + 0][j], qv, a0);
            a1 = fmaf(ksm[s0 + 1][j], qv, a1);
            a2 = fmaf(ksm[s0 + 2][j], qv, a2);
            a3 = fmaf(ksm[s0 + 3][j], qv, a3);
        }
        Asm[u][s0 + 0] = a0;  Asm[u][s0 + 1] = a1;
        Asm[u][s0 + 2] = a2;  Asm[u][s0 + 3] = a3;
    }
    __syncthreads();

    // outputs: thread -> i = tid&63, u in [ug*8, ug*8+8)
    const int i  = tid & 63;
    const int ug = tid >> 6;
    const float d  = sigmoidf_(op_decay[i]);
    const float d8 = ((d * d) * (d * d)) * ((d * d) * (d * d));
    float f = d;                          // dec^{u+1} at u = ug*8
    for (int e = 0; e < ug; e++) f *= d8;

    const size_t obase = ((size_t)(b * Tm + c * CH)) * ODm + i;
    for (int uu = 0; uu < 8; uu++) {
        const int u = ug * 8 + uu;
        float sq = 0.f;
        for (int j = 0; j < ODm; j++) sq = fmaf(Ssm[i][j], qsmT[j][u], sq);
        float acc = 0.f, g = 1.f;
        for (int s = u; s >= 0; s--) {
            acc = fmaf(Asm[u][s] * g, vsm[s][i], acc);
            g *= d;
        }
        g_bind[obase + (size_t)u * ODm] = fmaf(f, sq, acc);
        f *= d;
    }
}

// ------------------------------- layernorm -----------------------------------
__global__ __launch_bounds__(128) void ln_kernel(
    const float* __restrict__ ln_g, const float* __restrict__ ln_b,
    float* __restrict__ out)
{
    const int row = blockIdx.x;
    const int tid = threadIdx.x;
    const float4* yr = (const float4*)(g_y + (size_t)row * Dm);
    float4 v = yr[tid];
    float s  = v.x + v.y + v.z + v.w;
    float s2 = v.x * v.x + v.y * v.y + v.z * v.z + v.w * v.w;
    #pragma unroll
    for (int off = 16; off; off >>= 1) {
        s  += __shfl_xor_sync(0xffffffffu, s,  off);
        s2 += __shfl_xor_sync(0xffffffffu, s2, off);
    }
    __shared__ float ss[4], ss2[4];
    if ((tid & 31) == 0) { ss[tid >> 5] = s; ss2[tid >> 5] = s2; }
    __syncthreads();
    s  = ss[0]  + ss[1]  + ss[2]  + ss[3];
    s2 = ss2[0] + ss2[1] + ss2[2] + ss2[3];
    const float mu   = s  * (1.f / Dm);
    const float var  = s2 * (1.f / Dm) - mu * mu;
    const float rstd = rsqrtf(var + 1e-5f);
    float4 gg = ((const float4*)ln_g)[tid];
    float4 bb = ((const float4*)ln_b)[tid];
    float4 r;
    r.x = (v.x - mu) * rstd * gg.x + bb.x;
    r.y = (v.y - mu) * rstd * gg.y + bb.y;
    r.z = (v.z - mu) * rstd * gg.z + bb.z;
    r.w = (v.w - mu) * rstd * gg.w + bb.w;
    ((float4*)(out + (size_t)row * Dm))[tid] = r;
}

// --------------------------------- host --------------------------------------
extern "C" void kernel_launch(void* const* d_in, const int* in_sizes, int n_in,
                              void* d_out, int out_size)
{
    const float* x       = (const float*)d_in[0];
    const float* gate_W  = (const float*)d_in[1];
    const float* gate_b  = (const float*)d_in[2];
    const float* in_W    = (const float*)d_in[3];
    const float* in_b    = (const float*)d_in[4];
    const float* out_W   = (const float*)d_in[5];
    const float* out_b   = (const float*)d_in[6];
    const float* opv_W   = (const float*)d_in[7];
    const float* opv_b   = (const float*)d_in[8];
    const float* opk_W   = (const float*)d_in[9];
    const float* opk_b   = (const float*)d_in[10];
    const float* opq_W   = (const float*)d_in[11];
    const float* opq_b   = (const float*)d_in[12];
    const float* op_dec  = (const float*)d_in[13];
    const float* opout_W = (const float*)d_in[14];
    const float* opout_b = (const float*)d_in[15];
    const float* ln_g    = (const float*)d_in[16];
    const float* ln_b    = (const float*)d_in[17];
    float* out = (float*)d_out;

    float *p_lin, *p_states, *p_scanout, *p_bind, *p_y, *p_Wall, *p_ball;
    cudaGetSymbolAddress((void**)&p_lin,     g_lin);
    cudaGetSymbolAddress((void**)&p_states,  g_states);
    cudaGetSymbolAddress((void**)&p_scanout, g_scanout);
    cudaGetSymbolAddress((void**)&p_bind,    g_bind);
    cudaGetSymbolAddress((void**)&p_y,       g_y);
    cudaGetSymbolAddress((void**)&p_Wall,    g_Wall);
    cudaGetSymbolAddress((void**)&p_ball,    g_ball);

    const dim3 blk(256);

    // 0) pack fused weights
    pack_kernel<<<(Dm * NW + 255) / 256, blk>>>(
        gate_W, gate_b, in_W, in_b, opv_W, opv_b, opk_W, opk_b, opq_W, opq_b);
    // 1) lin = x @ W_all + b_all
    gemm_tc<<<dim3(NW / TNt, Mrows / TMt), blk>>>(
        x, p_Wall, p_ball, p_lin, Mrows, NW, Dm, 0, nullptr, nullptr);
    // 2) gated chunked scan
    scan1_kernel<<<(Bm * NCH * SDm) / 256, blk>>>();
    scan2_kernel<<<(Bm * SDm) / 64, 64>>>();
    scan3_kernel<<<(Bm * NCH * SDm) / 256, blk>>>();
    // 3) chunked binding scan
    bind1_kernel<<<dim3(NCH, Bm), blk>>>(op_dec);
    bind2_kernel<<<(Bm * ODm * ODm) / 256, blk>>>(op_dec);
    bind3_kernel<<<dim3(NCH, Bm), blk>>>(op_dec);
    // 4) scan_out = states @ out_W + out_b
    gemm_tc<<<dim3(Dm / TNt, Mrows / TMt), blk>>>(
        p_states, out_W, out_b, p_scanout, Mrows, Dm, SDm, 0, nullptr, nullptr);
    // 5) y = bind @ opout_W + opout_b + x + scan_out
    gemm_tc<<<dim3(Dm / TNt, Mrows / TMt), blk>>>(
        p_bind, opout_W, opout_b, p_y, Mrows, Dm, ODm, 3, x, p_scanout);
    // 6) layernorm -> out
    ln_kernel<<<Mrows, 128>>>(ln_g, ln_b, out);
}

// round 14
// speedup vs baseline: 4.5268x; 1.1339x over previous
#include <cuda_runtime.h>
#include <math.h>
#include <stdint.h>

// ---------------------------------------------------------------------------
// ParallelGatedScan  (B=8, T=2048, D=512, SD=256, OD=64, CHUNK=32)
//   pack:  W_all[512,768] = [gate_W | in_W | vW | kW | qW | zero-pad]
//   G1:    lin = x @ W_all + b_all            (tf32 tensor-core GEMM, prefetch)
//   scan1/2/3: gated chunked scan
//   bind1/2/3: CHUNKED binding scan
//   G2:    scan_out = states @ out_W + out_b  (tf32 GEMM)
//   G3:    y = bind @ opout_W + opout_b + x + scan_out  (tf32 GEMM, fused)
//   LN:    out = layernorm(y) * ln_g + ln_b
// ---------------------------------------------------------------------------

#define Bm 8
#define Tm 2048
#define Dm 512
#define SDm 256
#define ODm 64
#define NW 768                 // padded fused width (704 real)
#define NW_REAL 704
#define COL_IN 256
#define COL_V 512
#define COL_K 576
#define COL_Q 640
#define CH 32
#define NCH (Tm / CH)          // 64
#define Mrows (Bm * Tm)        // 16384

// ------------------------- scratch (device globals) ------------------------
__device__ float g_lin[Mrows * NW];          // 50 MB
__device__ float g_states[Mrows * SDm];
__device__ float g_scanout[Mrows * Dm];
__device__ float g_bind[Mrows * ODm];
__device__ float g_y[Mrows * Dm];
__device__ float g_ca[Bm * NCH * SDm];
__device__ float g_wb[Bm * NCH * SDm];
__device__ float g_hprev[Bm * NCH * SDm];
__device__ float g_Wall[Dm * NW];
__device__ float g_ball[NW];
__device__ float g_Sloc[Bm * NCH * ODm * ODm];   // 8.4 MB chunk summaries
__device__ float g_Sprev[Bm * NCH * ODm * ODm];  // 8.4 MB carried states

// --------------------------- weight packing ---------------------------------
__global__ void pack_kernel(
    const float* __restrict__ gW, const float* __restrict__ gb,
    const float* __restrict__ iW, const float* __restrict__ ib,
    const float* __restrict__ vW, const float* __restrict__ vb,
    const float* __restrict__ kW, const float* __restrict__ kb,
    const float* __restrict__ qW, const float* __restrict__ qb)
{
    int t = blockIdx.x * blockDim.x + threadIdx.x;
    if (t >= Dm * NW) return;
    int d = t / NW;
    int c = t % NW;
    float w = 0.f, bv = 0.f;
    if (c < COL_IN)        { w = gW[d * SDm + c];              bv = gb[c]; }
    else if (c < COL_V)    { w = iW[d * SDm + (c - COL_IN)];   bv = ib[c - COL_IN]; }
    else if (c < COL_K)    { w = vW[d * ODm + (c - COL_V)];    bv = vb[c - COL_V]; }
    else if (c < COL_Q)    { w = kW[d * ODm + (c - COL_K)];    bv = kb[c - COL_K]; }
    else if (c < NW_REAL)  { w = qW[d * ODm + (c - COL_Q)];    bv = qb[c - COL_Q]; }
    g_Wall[t] = w;
    if (d == 0) g_ball[c] = bv;
}

// ------------------------- tf32 tensor-core GEMM -----------------------------
// Software-pipelined: global loads for tile t+1 issued before compute of tile t.
#define TMt 128
#define TNt 128
#define TKt 32
#define AP  36
#define BP  136

__device__ __forceinline__ uint32_t f2tf(float f)
{
    uint32_t r;
    asm("cvt.rna.tf32.f32 %0, %1;" : "=r"(r) : "f"(f));
    return r;
}

__global__ __launch_bounds__(256) void gemm_tc(
    const float* __restrict__ A, const float* __restrict__ B,
    const float* __restrict__ bias, float* __restrict__ C,
    int M, int N, int K, int ep,
    const float* __restrict__ aux1, const float* __restrict__ aux2)
{
    __shared__ float As[TMt * AP];
    __shared__ float Bs[TKt * BP];

    const int tid  = threadIdx.x;
    const int bm   = blockIdx.y * TMt;
    const int bn   = blockIdx.x * TNt;
    const int lane = tid & 31;
    const int w    = tid >> 5;
    const int g    = lane >> 2;
    const int tig  = lane & 3;
    const int wm   = (w >> 2) * 64;
    const int wn   = (w & 3) * 32;

    float c[4][4][4];
    #pragma unroll
    for (int im = 0; im < 4; im++)
        #pragma unroll
        for (int in_ = 0; in_ < 4; in_++)
            #pragma unroll
            for (int r = 0; r < 4; r++) c[im][in_][r] = 0.f;

    const int nt = K / TKt;
    float4 av[4], bv4[4];
    #pragma unroll
    for (int j = 0; j < 4; j++) {
        int idx = j * 256 + tid;
        av[j]  = *(const float4*)&A[(size_t)(bm + (idx >> 3)) * K + ((idx & 7) << 2)];
        bv4[j] = *(const float4*)&B[(size_t)(idx >> 5) * N + bn + ((idx & 31) << 2)];
    }

    for (int t = 0; t < nt; t++) {
        __syncthreads();   // previous-iteration consumers done before overwrite
        #pragma unroll
        for (int j = 0; j < 4; j++) {
            int idx = j * 256 + tid;
            uint4 ua = { f2tf(av[j].x),  f2tf(av[j].y),  f2tf(av[j].z),  f2tf(av[j].w) };
            uint4 ub = { f2tf(bv4[j].x), f2tf(bv4[j].y), f2tf(bv4[j].z), f2tf(bv4[j].w) };
            *(uint4*)&As[(idx >> 3) * AP + ((idx & 7) << 2)]  = ua;
            *(uint4*)&Bs[(idx >> 5) * BP + ((idx & 31) << 2)] = ub;
        }
        __syncthreads();

        // issue next tile's global loads BEFORE compute (latency overlap)
        float4 av_n[4], bv_n[4];
        if (t + 1 < nt) {
            const int k1 = (t + 1) * TKt;
            #pragma unroll
            for (int j = 0; j < 4; j++) {
                int idx = j * 256 + tid;
                av_n[j] = *(const float4*)&A[(size_t)(bm + (idx >> 3)) * K + k1 + ((idx & 7) << 2)];
                bv_n[j] = *(const float4*)&B[(size_t)(k1 + (idx >> 5)) * N + bn + ((idx & 31) << 2)];
            }
        } else {
            #pragma unroll
            for (int j = 0; j < 4; j++) {
                av_n[j] = make_float4(0.f, 0.f, 0.f, 0.f);
                bv_n[j] = make_float4(0.f, 0.f, 0.f, 0.f);
            }
        }

        #pragma unroll
        for (int ks = 0; ks < 4; ks++) {
            const int kb = ks * 8;
            uint32_t af[4][4], bf[4][2];
            #pragma unroll
            for (int im = 0; im < 4; im++) {
                const int mb = wm + im * 16;
                af[im][0] = __float_as_uint(As[(mb + g)     * AP + kb + tig]);
                af[im][1] = __float_as_uint(As[(mb + g + 8) * AP + kb + tig]);
                af[im][2] = __float_as_uint(As[(mb + g)     * AP + kb + tig + 4]);
                af[im][3] = __float_as_uint(As[(mb + g + 8) * AP + kb + tig + 4]);
            }
            #pragma unroll
            for (int in_ = 0; in_ < 4; in_++) {
                const int nb = wn + in_ * 8;
                bf[in_][0] = __float_as_uint(Bs[(kb + tig)     * BP + nb + g]);
                bf[in_][1] = __float_as_uint(Bs[(kb + tig + 4) * BP + nb + g]);
            }
            #pragma unroll
            for (int im = 0; im < 4; im++)
                #pragma unroll
                for (int in_ = 0; in_ < 4; in_++)
                    asm volatile(
                        "mma.sync.aligned.m16n8k8.row.col.f32.tf32.tf32.f32 "
                        "{%0,%1,%2,%3},{%4,%5,%6,%7},{%8,%9},{%0,%1,%2,%3};"
                        : "+f"(c[im][in_][0]), "+f"(c[im][in_][1]),
                          "+f"(c[im][in_][2]), "+f"(c[im][in_][3])
                        : "r"(af[im][0]), "r"(af[im][1]), "r"(af[im][2]), "r"(af[im][3]),
                          "r"(bf[in_][0]), "r"(bf[in_][1]));
        }

        #pragma unroll
        for (int j = 0; j < 4; j++) { av[j] = av_n[j]; bv4[j] = bv_n[j]; }
    }

    #pragma unroll
    for (int im = 0; im < 4; im++) {
        const int r0 = bm + wm + im * 16 + g;
        #pragma unroll
        for (int in_ = 0; in_ < 4; in_++) {
            const int col = bn + wn + in_ * 8 + 2 * tig;
            const float b0 = bias[col], b1 = bias[col + 1];
            const size_t o0 = (size_t)r0 * N + col;
            const size_t o1 = (size_t)(r0 + 8) * N + col;
            float v0 = c[im][in_][0] + b0;
            float v1 = c[im][in_][1] + b1;
            float v2 = c[im][in_][2] + b0;
            float v3 = c[im][in_][3] + b1;
            if (ep == 3) {
                v0 += aux1[o0]     + aux2[o0];
                v1 += aux1[o0 + 1] + aux2[o0 + 1];
                v2 += aux1[o1]     + aux2[o1];
                v3 += aux1[o1 + 1] + aux2[o1 + 1];
            }
            float2 w0 = {v0, v1}, w1 = {v2, v3};
            *(float2*)&C[o0] = w0;
            *(float2*)&C[o1] = w1;
        }
    }
}

// ----------------------------- gated scan -----------------------------------
__device__ __forceinline__ float sigmoidf_(float z) { return 1.f / (1.f + expf(-z)); }

__global__ void scan1_kernel()
{
    int tid = blockIdx.x * blockDim.x + threadIdx.x;
    int sd = tid & (SDm - 1);
    int c  = (tid >> 8) & (NCH - 1);
    int b  = tid >> 14;
    size_t base = ((size_t)(b * Tm + c * CH)) * NW;
    float p = 1.f, wb = 0.f;
    for (int k = 0; k < CH; k++) {
        size_t ro = base + (size_t)k * NW;
        float g = sigmoidf_(g_lin[ro + sd]);
        float d = (1.f - g) * g_lin[ro + COL_IN + sd];
        p *= fmaxf(g, 1e-6f);
        wb += d / fmaxf(p, 1e-8f);
    }
    int cidx = (b * NCH + c) * SDm + sd;
    g_ca[cidx] = p;
    g_wb[cidx] = wb;
}

__global__ void scan2_kernel()
{
    int t  = blockIdx.x * blockDim.x + threadIdx.x;
    int sd = t & (SDm - 1);
    int b  = t >> 8;
    const int base = b * NCH * SDm + sd;
    float h  = 0.f;
    float ca = g_ca[base], wb = g_wb[base];
    #pragma unroll 8
    for (int c = 0; c < NCH; c++) {
        float ca_n = 0.f, wb_n = 0.f;
        if (c + 1 < NCH) {
            ca_n = g_ca[base + (c + 1) * SDm];
            wb_n = g_wb[base + (c + 1) * SDm];
        }
        g_hprev[base + c * SDm] = h;
        h = ca * (h + wb);
        ca = ca_n; wb = wb_n;
    }
}

__global__ void scan3_kernel()
{
    int tid = blockIdx.x * blockDim.x + threadIdx.x;
    int sd = tid & (SDm - 1);
    int c  = (tid >> 8) & (NCH - 1);
    int b  = tid >> 14;
    size_t base  = ((size_t)(b * Tm + c * CH)) * NW;
    size_t sbase = ((size_t)(b * Tm + c * CH)) * SDm + sd;
    int cidx = (b * NCH + c) * SDm + sd;
    float h = g_hprev[cidx];
    float p = 1.f, wb = 0.f;
    for (int k = 0; k < CH; k++) {
        size_t ro = base + (size_t)k * NW;
        float g = sigmoidf_(g_lin[ro + sd]);
        float d = (1.f - g) * g_lin[ro + COL_IN + sd];
        p *= fmaxf(g, 1e-6f);
        wb += d / fmaxf(p, 1e-8f);
        g_states[sbase + (size_t)k * SDm] = p * (h + wb);
    }
}

// ------------------------ chunked binding scan -------------------------------
// S_t[i][j] = dec_i S_{t-1}[i][j] + v_t[i] k_t[j];  o_t[i] = sum_j S_t[i][j] q_t[j]
__global__ __launch_bounds__(256) void bind1_kernel(const float* __restrict__ op_decay)
{
    const int c = blockIdx.x, b = blockIdx.y;
    const int tid = threadIdx.x;
    __shared__ float pw[CH + 1][ODm];
    __shared__ float ksm[CH][ODm];
    __shared__ float wsm[CH][ODm];

    if (tid < ODm) {
        float d = sigmoidf_(op_decay[tid]);
        float f = 1.f;
        for (int e = 0; e <= CH; e++) { pw[e][tid] = f; f *= d; }
    }
    __syncthreads();

    const size_t base = ((size_t)(b * Tm + c * CH)) * NW;
    for (int idx = tid; idx < CH * ODm; idx += 256) {
        int s = idx >> 6, i = idx & 63;
        ksm[s][i] = g_lin[base + (size_t)s * NW + COL_K + i];
        wsm[s][i] = g_lin[base + (size_t)s * NW + COL_V + i] * pw[31 - s][i];
    }
    __syncthreads();

    const int j  = tid & 63;
    const int ig = tid >> 6;
    float acc[16];
    #pragma unroll
    for (int r = 0; r < 16; r++) acc[r] = 0.f;
    for (int s = 0; s < CH; s++) {
        float kv = ksm[s][j];
        #pragma unroll
        for (int r = 0; r < 16; r++) acc[r] = fmaf(wsm[s][ig * 16 + r], kv, acc[r]);
    }
    float* dst = &g_Sloc[((size_t)(b * NCH + c)) * (ODm * ODm)];
    #pragma unroll
    for (int r = 0; r < 16; r++) dst[(ig * 16 + r) * ODm + j] = acc[r];
}

__global__ void bind2_kernel(const float* __restrict__ op_decay)
{
    int lane = blockIdx.x * blockDim.x + threadIdx.x;
    int b = lane >> 12;
    int i = (lane >> 6) & 63;
    float d = sigmoidf_(op_decay[i]);
    float d2 = d * d, d4 = d2 * d2, d8 = d4 * d4, d16 = d8 * d8, d32 = d16 * d16;
    const size_t base = (size_t)b * NCH * (ODm * ODm) + (lane & 4095);
    float h = 0.f;
    float sl = g_Sloc[base];
    #pragma unroll 8
    for (int c = 0; c < NCH; c++) {
        float sl_n = 0.f;
        if (c + 1 < NCH) sl_n = g_Sloc[base + (size_t)(c + 1) * (ODm * ODm)];
        g_Sprev[base + (size_t)c * (ODm * ODm)] = h;
        h = d32 * h + sl;
        sl = sl_n;
    }
}

__global__ __launch_bounds__(256) void bind3_kernel(const float* __restrict__ op_decay)
{
    const int c = blockIdx.x, b = blockIdx.y;
    const int tid = threadIdx.x;
    __shared__ float ksm[CH][ODm];
    __shared__ float qsmT[ODm][CH];
    __shared__ float vsm[CH][ODm];
    __shared__ float Ssm[ODm][ODm + 1];
    __shared__ float Asm[CH][CH + 1];

    const size_t base = ((size_t)(b * Tm + c * CH)) * NW;
    for (int idx = tid; idx < CH * ODm; idx += 256) {
        int s = idx >> 6, i = idx & 63;
        ksm[s][i]  = g_lin[base + (size_t)s * NW + COL_K + i];
        vsm[s][i]  = g_lin[base + (size_t)s * NW + COL_V + i];
        qsmT[i][s] = g_lin[base + (size_t)s * NW + COL_Q + i];
    }
    const float* Sp = &g_Sprev[((size_t)(b * NCH + c)) * (ODm * ODm)];
    for (int idx = tid; idx < ODm * ODm; idx += 256) {
        Ssm[idx >> 6][idx & 63] = Sp[idx];
    }
    __syncthreads();

    {
        const int u  = tid & 31;
        const int s0 = (tid >> 5) * 4;
        float a0 = 0.f, a1 = 0.f, a2 = 0.f, a3 = 0.f;
        for (int j = 0; j < ODm; j++) {
            float qv = qsmT[j][u];
            a0 = fmaf(ksm[s0 + 0][j], qv, a0);
            a1 = fmaf(ksm[s0 + 1][j], qv, a1);
            a2 = fmaf(ksm[s0 + 2][j], qv, a2);
            a3 = fmaf(ksm[s0 + 3][j], qv, a3);
        }
        Asm[u][s0 + 0] = a0;  Asm[u][s0 + 1] = a1;
        Asm[u][s0 + 2] = a2;  Asm[u][s0 + 3] = a3;
    }
    __syncthreads();

    const int i  = tid & 63;
    const int ug = tid >> 6;
    const float d  = sigmoidf_(op_decay[i]);
    const float d8 = ((d * d) * (d * d)) * ((d * d) * (d * d));
    float f = d;
    for (int e = 0; e < ug; e++) f *= d8;

    const size_t obase = ((size_t)(b * Tm + c * CH)) * ODm + i;
    for (int uu = 0; uu < 8; uu++) {
        const int u = ug * 8 + uu;
        float sq = 0.f;
        for (int j = 0; j < ODm; j++) sq = fmaf(Ssm[i][j], qsmT[j][u], sq);
        float acc = 0.f, g = 1.f;
        for (int s = u; s >= 0; s--) {
            acc = fmaf(Asm[u][s] * g, vsm[s][i], acc);
            g *= d;
        }
        g_bind[obase + (size_t)u * ODm] = fmaf(f, sq, acc);
        f *= d;
    }
}

// ------------------------------- layernorm -----------------------------------
__global__ __launch_bounds__(128) void ln_kernel(
    const float* __restrict__ ln_g, const float* __restrict__ ln_b,
    float* __restrict__ out)
{
    const int row = blockIdx.x;
    const int tid = threadIdx.x;
    const float4* yr = (const float4*)(g_y + (size_t)row * Dm);
    float4 v = yr[tid];
    float s  = v.x + v.y + v.z + v.w;
    float s2 = v.x * v.x + v.y * v.y + v.z * v.z + v.w * v.w;
    #pragma unroll
    for (int off = 16; off; off >>= 1) {
        s  += __shfl_xor_sync(0xffffffffu, s,  off);
        s2 += __shfl_xor_sync(0xffffffffu, s2, off);
    }
    __shared__ float ss[4], ss2[4];
    if ((tid & 31) == 0) { ss[tid >> 5] = s; ss2[tid >> 5] = s2; }
    __syncthreads();
    s  = ss[0]  + ss[1]  + ss[2]  + ss[3];
    s2 = ss2[0] + ss2[1] + ss2[2] + ss2[3];
    const float mu   = s  * (1.f / Dm);
    const float var  = s2 * (1.f / Dm) - mu * mu;
    const float rstd = rsqrtf(var + 1e-5f);
    float4 gg = ((const float4*)ln_g)[tid];
    float4 bb = ((const float4*)ln_b)[tid];
    float4 r;
    r.x = (v.x - mu) * rstd * gg.x + bb.x;
    r.y = (v.y - mu) * rstd * gg.y + bb.y;
    r.z = (v.z - mu) * rstd * gg.z + bb.z;
    r.w = (v.w - mu) * rstd * gg.w + bb.w;
    ((float4*)(out + (size_t)row * Dm))[tid] = r;
}

// --------------------------------- host --------------------------------------
extern "C" void kernel_launch(void* const* d_in, const int* in_sizes, int n_in,
                              void* d_out, int out_size)
{
    const float* x       = (const float*)d_in[0];
    const float* gate_W  = (const float*)d_in[1];
    const float* gate_b  = (const float*)d_in[2];
    const float* in_W    = (const float*)d_in[3];
    const float* in_b    = (const float*)d_in[4];
    const float* out_W   = (const float*)d_in[5];
    const float* out_b   = (const float*)d_in[6];
    const float* opv_W   = (const float*)d_in[7];
    const float* opv_b   = (const float*)d_in[8];
    const float* opk_W   = (const float*)d_in[9];
    const float* opk_b   = (const float*)d_in[10];
    const float* opq_W   = (const float*)d_in[11];
    const float* opq_b   = (const float*)d_in[12];
    const float* op_dec  = (const float*)d_in[13];
    const float* opout_W = (const float*)d_in[14];
    const float* opout_b = (const float*)d_in[15];
    const float* ln_g    = (const float*)d_in[16];
    const float* ln_b    = (const float*)d_in[17];
    float* out = (float*)d_out;

    float *p_lin, *p_states, *p_scanout, *p_bind, *p_y, *p_Wall, *p_ball;
    cudaGetSymbolAddress((void**)&p_lin,     g_lin);
    cudaGetSymbolAddress((void**)&p_states,  g_states);
    cudaGetSymbolAddress((void**)&p_scanout, g_scanout);
    cudaGetSymbolAddress((void**)&p_bind,    g_bind);
    cudaGetSymbolAddress((void**)&p_y,       g_y);
    cudaGetSymbolAddress((void**)&p_Wall,    g_Wall);
    cudaGetSymbolAddress((void**)&p_ball,    g_ball);

    const dim3 blk(256);

    // 0) pack fused weights
    pack_kernel<<<(Dm * NW + 255) / 256, blk>>>(
        gate_W, gate_b, in_W, in_b, opv_W, opv_b, opk_W, opk_b, opq_W, opq_b);
    // 1) lin = x @ W_all + b_all
    gemm_tc<<<dim3(NW / TNt, Mrows / TMt), blk>>>(
        x, p_Wall, p_ball, p_lin, Mrows, NW, Dm, 0, nullptr, nullptr);
    // 2) gated chunked scan
    scan1_kernel<<<(Bm * NCH * SDm) / 256, blk>>>();
    scan2_kernel<<<(Bm * SDm) / 64, 64>>>();
    scan3_kernel<<<(Bm * NCH * SDm) / 256, blk>>>();
    // 3) chunked binding scan
    bind1_kernel<<<dim3(NCH, Bm), blk>>>(op_dec);
    bind2_kernel<<<(Bm * ODm * ODm) / 256, blk>>>(op_dec);
    bind3_kernel<<<dim3(NCH, Bm), blk>>>(op_dec);
    // 4) scan_out = states @ out_W + out_b
    gemm_tc<<<dim3(Dm / TNt, Mrows / TMt), blk>>>(
        p_states, out_W, out_b, p_scanout, Mrows, Dm, SDm, 0, nullptr, nullptr);
    // 5) y = bind @ opout_W + opout_b + x + scan_out
    gemm_tc<<<dim3(Dm / TNt, Mrows / TMt), blk>>>(
        p_bind, opout_W, opout_b, p_y, Mrows, Dm, ODm, 3, x, p_scanout);
    // 6) layernorm -> out
    ln_kernel<<<Mrows, 128>>>(ln_g, ln_b, out);
}

// round 16
// speedup vs baseline: 5.1345x; 1.1342x over previous
#include <cuda_runtime.h>
#include <cuda_fp16.h>
#include <math.h>
#include <stdint.h>

// ---------------------------------------------------------------------------
// ParallelGatedScan  (B=8, T=2048, D=512, SD=256, OD=64, CHUNK=32)
//   pack:  W_all[512,768] = [gate_W | in_W | vW | kW | qW | zero-pad]
//   G1:    lin = x @ W_all + b_all            (fp16 tensor-core GEMM, prefetch)
//   scan1/2/3: gated chunked scan
//   bind1/2/3: CHUNKED binding scan
//   G2:    scan_out = states @ out_W + out_b  (fp16 GEMM)
//   G3:    y = bind @ opout_W + opout_b + x + scan_out  (fp16 GEMM, fused)
//   LN:    out = layernorm(y) * ln_g + ln_b
// ---------------------------------------------------------------------------

#define Bm 8
#define Tm 2048
#define Dm 512
#define SDm 256
#define ODm 64
#define NW 768                 // padded fused width (704 real)
#define NW_REAL 704
#define COL_IN 256
#define COL_V 512
#define COL_K 576
#define COL_Q 640
#define CH 32
#define NCH (Tm / CH)          // 64
#define Mrows (Bm * Tm)        // 16384

// ------------------------- scratch (device globals) ------------------------
__device__ float g_lin[Mrows * NW];          // 50 MB
__device__ float g_states[Mrows * SDm];
__device__ float g_scanout[Mrows * Dm];
__device__ float g_bind[Mrows * ODm];
__device__ float g_y[Mrows * Dm];
__device__ float g_ca[Bm * NCH * SDm];
__device__ float g_wb[Bm * NCH * SDm];
__device__ float g_hprev[Bm * NCH * SDm];
__device__ float g_Wall[Dm * NW];
__device__ float g_ball[NW];
__device__ float g_Sloc[Bm * NCH * ODm * ODm];
__device__ float g_Sprev[Bm * NCH * ODm * ODm];

// --------------------------- weight packing ---------------------------------
__global__ void pack_kernel(
    const float* __restrict__ gW, const float* __restrict__ gb,
    const float* __restrict__ iW, const float* __restrict__ ib,
    const float* __restrict__ vW, const float* __restrict__ vb,
    const float* __restrict__ kW, const float* __restrict__ kb,
    const float* __restrict__ qW, const float* __restrict__ qb)
{
    int t = blockIdx.x * blockDim.x + threadIdx.x;
    if (t >= Dm * NW) return;
    int d = t / NW;
    int c = t % NW;
    float w = 0.f, bv = 0.f;
    if (c < COL_IN)        { w = gW[d * SDm + c];              bv = gb[c]; }
    else if (c < COL_V)    { w = iW[d * SDm + (c - COL_IN)];   bv = ib[c - COL_IN]; }
    else if (c < COL_K)    { w = vW[d * ODm + (c - COL_V)];    bv = vb[c - COL_V]; }
    else if (c < COL_Q)    { w = kW[d * ODm + (c - COL_K)];    bv = kb[c - COL_K]; }
    else if (c < NW_REAL)  { w = qW[d * ODm + (c - COL_Q)];    bv = qb[c - COL_Q]; }
    g_Wall[t] = w;
    if (d == 0) g_ball[c] = bv;
}

// ------------------------- fp16 tensor-core GEMM -----------------------------
// C[M,N] = A[M,K] @ B[K,N]; block tile 128x128x32; 8 warps 2x4; warp 64x32.
// mma.sync.aligned.m16n8k16 f16 (fp32 accum). fp16 mantissa == tf32 mantissa.
// A smem: half2 [m][k/2] pitch P2A; B smem: k-pair-interleaved half2 [k/2][n].
#define TMt 128
#define TNt 128
#define TKt 32
#define P2A 20      // A frag bank = (20g+tig)%32, all distinct
#define P2B 136     // B frag bank = (8tig+g)%32, all distinct

__global__ __launch_bounds__(256) void gemm_tc(
    const float* __restrict__ A, const float* __restrict__ B,
    const float* __restrict__ bias, float* __restrict__ C,
    int M, int N, int K, int ep,
    const float* __restrict__ aux1, const float* __restrict__ aux2)
{
    __shared__ __half2 As2[TMt * P2A];          // 10.2 KB
    __shared__ __half2 Bs2[(TKt / 2) * P2B];    // 8.7 KB

    const int tid  = threadIdx.x;
    const int bm   = blockIdx.y * TMt;
    const int bn   = blockIdx.x * TNt;
    const int lane = tid & 31;
    const int w    = tid >> 5;
    const int g    = lane >> 2;
    const int tig  = lane & 3;
    const int wm   = (w >> 2) * 64;
    const int wn   = (w & 3) * 32;

    float c[4][4][4];
    #pragma unroll
    for (int im = 0; im < 4; im++)
        #pragma unroll
        for (int in_ = 0; in_ < 4; in_++)
            #pragma unroll
            for (int r = 0; r < 4; r++) c[im][in_][r] = 0.f;

    const int nt = K / TKt;

    // staging registers (tile t)
    float4 av[4];          // A: idx=j*256+tid -> row idx>>3, kcol (idx&7)*4
    float4 be[2], bo[2];   // B: idx=j*256+tid -> kpair idx>>5, n0 (idx&31)*4

    #pragma unroll
    for (int j = 0; j < 4; j++) {
        int idx = j * 256 + tid;
        av[j] = *(const float4*)&A[(size_t)(bm + (idx >> 3)) * K + ((idx & 7) << 2)];
    }
    #pragma unroll
    for (int j = 0; j < 2; j++) {
        int idx = j * 256 + tid;
        int r = idx >> 5, n0 = (idx & 31) << 2;
        be[j] = *(const float4*)&B[(size_t)(2 * r)     * N + bn + n0];
        bo[j] = *(const float4*)&B[(size_t)(2 * r + 1) * N + bn + n0];
    }

    for (int t = 0; t < nt; t++) {
        __syncthreads();   // previous-iteration consumers done before overwrite
        #pragma unroll
        for (int j = 0; j < 4; j++) {
            int idx = j * 256 + tid;
            __half2 h0 = __floats2half2_rn(av[j].x, av[j].y);
            __half2 h1 = __floats2half2_rn(av[j].z, av[j].w);
            uint2 pk = { *(uint32_t*)&h0, *(uint32_t*)&h1 };
            *(uint2*)&As2[(idx >> 3) * P2A + ((idx & 7) << 1)] = pk;
        }
        #pragma unroll
        for (int j = 0; j < 2; j++) {
            int idx = j * 256 + tid;
            int r = idx >> 5, n0 = (idx & 31) << 2;
            __half2 c0 = __floats2half2_rn(be[j].x, bo[j].x);
            __half2 c1 = __floats2half2_rn(be[j].y, bo[j].y);
            __half2 c2 = __floats2half2_rn(be[j].z, bo[j].z);
            __half2 c3 = __floats2half2_rn(be[j].w, bo[j].w);
            uint4 pk = { *(uint32_t*)&c0, *(uint32_t*)&c1,
                         *(uint32_t*)&c2, *(uint32_t*)&c3 };
            *(uint4*)&Bs2[r * P2B + n0] = pk;
        }
        __syncthreads();

        // prefetch next tile's global loads BEFORE compute (latency overlap)
        float4 av_n[4], be_n[2], bo_n[2];
        if (t + 1 < nt) {
            const int k1 = (t + 1) * TKt;
            #pragma unroll
            for (int j = 0; j < 4; j++) {
                int idx = j * 256 + tid;
                av_n[j] = *(const float4*)&A[(size_t)(bm + (idx >> 3)) * K + k1 + ((idx & 7) << 2)];
            }
            #pragma unroll
            for (int j = 0; j < 2; j++) {
                int idx = j * 256 + tid;
                int r = idx >> 5, n0 = (idx & 31) << 2;
                be_n[j] = *(const float4*)&B[(size_t)(k1 + 2 * r)     * N + bn + n0];
                bo_n[j] = *(const float4*)&B[(size_t)(k1 + 2 * r + 1) * N + bn + n0];
            }
        } else {
            #pragma unroll
            for (int j = 0; j < 4; j++) av_n[j] = make_float4(0.f, 0.f, 0.f, 0.f);
            #pragma unroll
            for (int j = 0; j < 2; j++) {
                be_n[j] = make_float4(0.f, 0.f, 0.f, 0.f);
                bo_n[j] = make_float4(0.f, 0.f, 0.f, 0.f);
            }
        }

        #pragma unroll
        for (int ks = 0; ks < 2; ks++) {
            const int kb = ks * 8;               // half2 offset of this k16 step
            uint32_t af[4][4], bf[4][2];
            #pragma unroll
            for (int im = 0; im < 4; im++) {
                const int mb = wm + im * 16;
                af[im][0] = *(const uint32_t*)&As2[(mb + g)     * P2A + kb + tig];
                af[im][1] = *(const uint32_t*)&As2[(mb + g + 8) * P2A + kb + tig];
                af[im][2] = *(const uint32_t*)&As2[(mb + g)     * P2A + kb + tig + 4];
                af[im][3] = *(const uint32_t*)&As2[(mb + g + 8) * P2A + kb + tig + 4];
            }
            #pragma unroll
            for (int in_ = 0; in_ < 4; in_++) {
                const int nb = wn + in_ * 8;
                bf[in_][0] = *(const uint32_t*)&Bs2[(kb + tig)     * P2B + nb + g];
                bf[in_][1] = *(const uint32_t*)&Bs2[(kb + tig + 4) * P2B + nb + g];
            }
            #pragma unroll
            for (int im = 0; im < 4; im++)
                #pragma unroll
                for (int in_ = 0; in_ < 4; in_++)
                    asm volatile(
                        "mma.sync.aligned.m16n8k16.row.col.f32.f16.f16.f32 "
                        "{%0,%1,%2,%3},{%4,%5,%6,%7},{%8,%9},{%0,%1,%2,%3};"
                        : "+f"(c[im][in_][0]), "+f"(c[im][in_][1]),
                          "+f"(c[im][in_][2]), "+f"(c[im][in_][3])
                        : "r"(af[im][0]), "r"(af[im][1]), "r"(af[im][2]), "r"(af[im][3]),
                          "r"(bf[in_][0]), "r"(bf[in_][1]));
        }

        #pragma unroll
        for (int j = 0; j < 4; j++) av[j] = av_n[j];
        #pragma unroll
        for (int j = 0; j < 2; j++) { be[j] = be_n[j]; bo[j] = bo_n[j]; }
    }

    #pragma unroll
    for (int im = 0; im < 4; im++) {
        const int r0 = bm + wm + im * 16 + g;
        #pragma unroll
        for (int in_ = 0; in_ < 4; in_++) {
            const int col = bn + wn + in_ * 8 + 2 * tig;
            const float b0 = bias[col], b1 = bias[col + 1];
            const size_t o0 = (size_t)r0 * N + col;
            const size_t o1 = (size_t)(r0 + 8) * N + col;
            float v0 = c[im][in_][0] + b0;
            float v1 = c[im][in_][1] + b1;
            float v2 = c[im][in_][2] + b0;
            float v3 = c[im][in_][3] + b1;
            if (ep == 3) {
                v0 += aux1[o0]     + aux2[o0];
                v1 += aux1[o0 + 1] + aux2[o0 + 1];
                v2 += aux1[o1]     + aux2[o1];
                v3 += aux1[o1 + 1] + aux2[o1 + 1];
            }
            float2 w0 = {v0, v1}, w1 = {v2, v3};
            *(float2*)&C[o0] = w0;
            *(float2*)&C[o1] = w1;
        }
    }
}

// ----------------------------- gated scan -----------------------------------
__device__ __forceinline__ float sigmoidf_(float z) { return 1.f / (1.f + expf(-z)); }

__global__ void scan1_kernel()
{
    int tid = blockIdx.x * blockDim.x + threadIdx.x;
    int sd = tid & (SDm - 1);
    int c  = (tid >> 8) & (NCH - 1);
    int b  = tid >> 14;
    size_t base = ((size_t)(b * Tm + c * CH)) * NW;
    float p = 1.f, wb = 0.f;
    for (int k = 0; k < CH; k++) {
        size_t ro = base + (size_t)k * NW;
        float g = sigmoidf_(g_lin[ro + sd]);
        float d = (1.f - g) * g_lin[ro + COL_IN + sd];
        p *= fmaxf(g, 1e-6f);
        wb += d / fmaxf(p, 1e-8f);
    }
    int cidx = (b * NCH + c) * SDm + sd;
    g_ca[cidx] = p;
    g_wb[cidx] = wb;
}

__global__ void scan2_kernel()
{
    int t  = blockIdx.x * blockDim.x + threadIdx.x;
    int sd = t & (SDm - 1);
    int b  = t >> 8;
    const int base = b * NCH * SDm + sd;
    float h  = 0.f;
    float ca = g_ca[base], wb = g_wb[base];
    #pragma unroll 8
    for (int c = 0; c < NCH; c++) {
        float ca_n = 0.f, wb_n = 0.f;
        if (c + 1 < NCH) {
            ca_n = g_ca[base + (c + 1) * SDm];
            wb_n = g_wb[base + (c + 1) * SDm];
        }
        g_hprev[base + c * SDm] = h;
        h = ca * (h + wb);
        ca = ca_n; wb = wb_n;
    }
}

__global__ void scan3_kernel()
{
    int tid = blockIdx.x * blockDim.x + threadIdx.x;
    int sd = tid & (SDm - 1);
    int c  = (tid >> 8) & (NCH - 1);
    int b  = tid >> 14;
    size_t base  = ((size_t)(b * Tm + c * CH)) * NW;
    size_t sbase = ((size_t)(b * Tm + c * CH)) * SDm + sd;
    int cidx = (b * NCH + c) * SDm + sd;
    float h = g_hprev[cidx];
    float p = 1.f, wb = 0.f;
    for (int k = 0; k < CH; k++) {
        size_t ro = base + (size_t)k * NW;
        float g = sigmoidf_(g_lin[ro + sd]);
        float d = (1.f - g) * g_lin[ro + COL_IN + sd];
        p *= fmaxf(g, 1e-6f);
        wb += d / fmaxf(p, 1e-8f);
        g_states[sbase + (size_t)k * SDm] = p * (h + wb);
    }
}

// ------------------------ chunked binding scan -------------------------------
__global__ __launch_bounds__(256) void bind1_kernel(const float* __restrict__ op_decay)
{
    const int c = blockIdx.x, b = blockIdx.y;
    const int tid = threadIdx.x;
    __shared__ float pw[CH + 1][ODm];
    __shared__ float ksm[CH][ODm];
    __shared__ float wsm[CH][ODm];

    if (tid < ODm) {
        float d = sigmoidf_(op_decay[tid]);
        float f = 1.f;
        for (int e = 0; e <= CH; e++) { pw[e][tid] = f; f *= d; }
    }
    __syncthreads();

    const size_t base = ((size_t)(b * Tm + c * CH)) * NW;
    for (int idx = tid; idx < CH * ODm; idx += 256) {
        int s = idx >> 6, i = idx & 63;
        ksm[s][i] = g_lin[base + (size_t)s * NW + COL_K + i];
        wsm[s][i] = g_lin[base + (size_t)s * NW + COL_V + i] * pw[31 - s][i];
    }
    __syncthreads();

    const int j  = tid & 63;
    const int ig = tid >> 6;
    float acc[16];
    #pragma unroll
    for (int r = 0; r < 16; r++) acc[r] = 0.f;
    for (int s = 0; s < CH; s++) {
        float kv = ksm[s][j];
        #pragma unroll
        for (int r = 0; r < 16; r++) acc[r] = fmaf(wsm[s][ig * 16 + r], kv, acc[r]);
    }
    float* dst = &g_Sloc[((size_t)(b * NCH + c)) * (ODm * ODm)];
    #pragma unroll
    for (int r = 0; r < 16; r++) dst[(ig * 16 + r) * ODm + j] = acc[r];
}

__global__ void bind2_kernel(const float* __restrict__ op_decay)
{
    int lane = blockIdx.x * blockDim.x + threadIdx.x;
    int b = lane >> 12;
    int i = (lane >> 6) & 63;
    float d = sigmoidf_(op_decay[i]);
    float d2 = d * d, d4 = d2 * d2, d8 = d4 * d4, d16 = d8 * d8, d32 = d16 * d16;
    const size_t base = (size_t)b * NCH * (ODm * ODm) + (lane & 4095);
    float h = 0.f;
    float sl = g_Sloc[base];
    #pragma unroll 8
    for (int c = 0; c < NCH; c++) {
        float sl_n = 0.f;
        if (c + 1 < NCH) sl_n = g_Sloc[base + (size_t)(c + 1) * (ODm * ODm)];
        g_Sprev[base + (size_t)c * (ODm * ODm)] = h;
        h = d32 * h + sl;
        sl = sl_n;
    }
}

__global__ __launch_bounds__(256) void bind3_kernel(const float* __restrict__ op_decay)
{
    const int c = blockIdx.x, b = blockIdx.y;
    const int tid = threadIdx.x;
    __shared__ float ksm[CH][ODm];
    __shared__ float qsmT[ODm][CH];
    __shared__ float vsm[CH][ODm];
    __shared__ float Ssm[ODm][ODm + 1];
    __shared__ float Asm[CH][CH + 1];

    const size_t base = ((size_t)(b * Tm + c * CH)) * NW;
    for (int idx = tid; idx < CH * ODm; idx += 256) {
        int s = idx >> 6, i = idx & 63;
        ksm[s][i]  = g_lin[base + (size_t)s * NW + COL_K + i];
        vsm[s][i]  = g_lin[base + (size_t)s * NW + COL_V + i];
        qsmT[i][s] = g_lin[base + (size_t)s * NW + COL_Q + i];
    }
    const float* Sp = &g_Sprev[((size_t)(b * NCH + c)) * (ODm * ODm)];
    for (int idx = tid; idx < ODm * ODm; idx += 256) {
        Ssm[idx >> 6][idx & 63] = Sp[idx];
    }
    __syncthreads();

    {
        const int u  = tid & 31;
        const int s0 = (tid >> 5) * 4;
        float a0 = 0.f, a1 = 0.f, a2 = 0.f, a3 = 0.f;
        for (int j = 0; j < ODm; j++) {
            float qv = qsmT[j][u];
            a0 = fmaf(ksm[s0 + 0][j], qv, a0);
            a1 = fmaf(ksm[s0 + 1][j], qv, a1);
            a2 = fmaf(ksm[s0 + 2][j], qv, a2);
            a3 = fmaf(ksm[s0 + 3][j], qv, a3);
        }
        Asm[u][s0 + 0] = a0;  Asm[u][s0 + 1] = a1;
        Asm[u][s0 + 2] = a2;  Asm[u][s0 + 3] = a3;
    }
    __syncthreads();

    const int i  = tid & 63;
    const int ug = tid >> 6;
    const float d  = sigmoidf_(op_decay[i]);
    const float d8 = ((d * d) * (d * d)) * ((d * d) * (d * d));
    float f = d;
    for (int e = 0; e < ug; e++) f *= d8;

    const size_t obase = ((size_t)(b * Tm + c * CH)) * ODm + i;
    for (int uu = 0; uu < 8; uu++) {
        const int u = ug * 8 + uu;
        float sq = 0.f;
        for (int j = 0; j < ODm; j++) sq = fmaf(Ssm[i][j], qsmT[j][u], sq);
        float acc = 0.f, g = 1.f;
        for (int s = u; s >= 0; s--) {
            acc = fmaf(Asm[u][s] * g, vsm[s][i], acc);
            g *= d;
        }
        g_bind[obase + (size_t)u * ODm] = fmaf(f, sq, acc);
        f *= d;
    }
}

// ------------------------------- layernorm -----------------------------------
__global__ __launch_bounds__(128) void ln_kernel(
    const float* __restrict__ ln_g, const float* __restrict__ ln_b,
    float* __restrict__ out)
{
    const int row = blockIdx.x;
    const int tid = threadIdx.x;
    const float4* yr = (const float4*)(g_y + (size_t)row * Dm);
    float4 v = yr[tid];
    float s  = v.x + v.y + v.z + v.w;
    float s2 = v.x * v.x + v.y * v.y + v.z * v.z + v.w * v.w;
    #pragma unroll
    for (int off = 16; off; off >>= 1) {
        s  += __shfl_xor_sync(0xffffffffu, s,  off);
        s2 += __shfl_xor_sync(0xffffffffu, s2, off);
    }
    __shared__ float ss[4], ss2[4];
    if ((tid & 31) == 0) { ss[tid >> 5] = s; ss2[tid >> 5] = s2; }
    __syncthreads();
    s  = ss[0]  + ss[1]  + ss[2]  + ss[3];
    s2 = ss2[0] + ss2[1] + ss2[2] + ss2[3];
    const float mu   = s  * (1.f / Dm);
    const float var  = s2 * (1.f / Dm) - mu * mu;
    const float rstd = rsqrtf(var + 1e-5f);
    float4 gg = ((const float4*)ln_g)[tid];
    float4 bb = ((const float4*)ln_b)[tid];
    float4 r;
    r.x = (v.x - mu) * rstd * gg.x + bb.x;
    r.y = (v.y - mu) * rstd * gg.y + bb.y;
    r.z = (v.z - mu) * rstd * gg.z + bb.z;
    r.w = (v.w - mu) * rstd * gg.w + bb.w;
    ((float4*)(out + (size_t)row * Dm))[tid] = r;
}

// --------------------------------- host --------------------------------------
extern "C" void kernel_launch(void* const* d_in, const int* in_sizes, int n_in,
                              void* d_out, int out_size)
{
    const float* x       = (const float*)d_in[0];
    const float* gate_W  = (const float*)d_in[1];
    const float* gate_b  = (const float*)d_in[2];
    const float* in_W    = (const float*)d_in[3];
    const float* in_b    = (const float*)d_in[4];
    const float* out_W   = (const float*)d_in[5];
    const float* out_b   = (const float*)d_in[6];
    const float* opv_W   = (const float*)d_in[7];
    const float* opv_b   = (const float*)d_in[8];
    const float* opk_W   = (const float*)d_in[9];
    const float* opk_b   = (const float*)d_in[10];
    const float* opq_W   = (const float*)d_in[11];
    const float* opq_b   = (const float*)d_in[12];
    const float* op_dec  = (const float*)d_in[13];
    const float* opout_W = (const float*)d_in[14];
    const float* opout_b = (const float*)d_in[15];
    const float* ln_g    = (const float*)d_in[16];
    const float* ln_b    = (const float*)d_in[17];
    float* out = (float*)d_out;

    float *p_lin, *p_states, *p_scanout, *p_bind, *p_y, *p_Wall, *p_ball;
    cudaGetSymbolAddress((void**)&p_lin,     g_lin);
    cudaGetSymbolAddress((void**)&p_states,  g_states);
    cudaGetSymbolAddress((void**)&p_scanout, g_scanout);
    cudaGetSymbolAddress((void**)&p_bind,    g_bind);
    cudaGetSymbolAddress((void**)&p_y,       g_y);
    cudaGetSymbolAddress((void**)&p_Wall,    g_Wall);
    cudaGetSymbolAddress((void**)&p_ball,    g_ball);

    const dim3 blk(256);

    // 0) pack fused weights
    pack_kernel<<<(Dm * NW + 255) / 256, blk>>>(
        gate_W, gate_b, in_W, in_b, opv_W, opv_b, opk_W, opk_b, opq_W, opq_b);
    // 1) lin = x @ W_all + b_all
    gemm_tc<<<dim3(NW / TNt, Mrows / TMt), blk>>>(
        x, p_Wall, p_ball, p_lin, Mrows, NW, Dm, 0, nullptr, nullptr);
    // 2) gated chunked scan
    scan1_kernel<<<(Bm * NCH * SDm) / 256, blk>>>();
    scan2_kernel<<<(Bm * SDm) / 64, 64>>>();
    scan3_kernel<<<(Bm * NCH * SDm) / 256, blk>>>();
    // 3) chunked binding scan
    bind1_kernel<<<dim3(NCH, Bm), blk>>>(op_dec);
    bind2_kernel<<<(Bm * ODm * ODm) / 256, blk>>>(op_dec);
    bind3_kernel<<<dim3(NCH, Bm), blk>>>(op_dec);
    // 4) scan_out = states @ out_W + out_b
    gemm_tc<<<dim3(Dm / TNt, Mrows / TMt), blk>>>(
        p_states, out_W, out_b, p_scanout, Mrows, Dm, SDm, 0, nullptr, nullptr);
    // 5) y = bind @ opout_W + opout_b + x + scan_out
    gemm_tc<<<dim3(Dm / TNt, Mrows / TMt), blk>>>(
        p_bind, opout_W, opout_b, p_y, Mrows, Dm, ODm, 3, x, p_scanout);
    // 6) layernorm -> out
    ln_kernel<<<Mrows, 128>>>(ln_g, ln_b, out);
}